// round 7
// baseline (speedup 1.0000x reference)
#include <cuda_runtime.h>
#include <cuda_bf16.h>
#include <mma.h>
#include <cstddef>
using namespace nvcuda;

// ---------------------------------------------------------------------------
// Shapes: B=8 TIN=1040 IN=80 TRI=128 D=512 FFN=2048 L=8 OUT=1024
// H=8 DH=64 STRIDE=4 SEG=16 RC=4 LC=32 MAXMEM=4
// Tr=260 U=256 nseg=16 Rt=64 Q=336 K=335
// ---------------------------------------------------------------------------

#define NB 8
#define DMODEL 512
#define QROWS 336
#define KROWS 335
#define STROWS 320
#define TRROWS 260
#define NSEG 16
#define NMEMS 15
#define FFND 2048
#define OUTD 1024

#define MQ   (QROWS * NB)          // 2688 (multiple of 128)
#define MKP  2688                  // kin padded rows (2680 -> 2688)
#define MST  (STROWS * NB)         // 2560 (multiple of 128)

// fp32 scratch
__device__ float g_x[TRROWS * NB * DMODEL];
__device__ float g_state[STROWS * NB * DMODEL];
__device__ float g_state2[STROWS * NB * DMODEL];
__device__ float g_qin[QROWS * NB * DMODEL];     // LN fp32 (summary input)
__device__ float g_q[MQ * DMODEL];
__device__ float g_k[MKP * DMODEL];
__device__ float g_v[MKP * DMODEL];
__device__ float g_att[MQ * DMODEL];
__device__ float g_out[MQ * DMODEL];
__device__ float g_f1raw[MST * FFND];
__device__ float g_f2raw[MST * DMODEL];
__device__ float g_yt[2048 * OUTD];

// bf16 hi/lo activation buffers (zero-initialized -> pad rows are 0)
__device__ __nv_bfloat16 g_qin_h[MQ * DMODEL],  g_qin_l[MQ * DMODEL];
__device__ __nv_bfloat16 g_kin_h[MKP * DMODEL], g_kin_l[MKP * DMODEL];
__device__ __nv_bfloat16 g_att_h[MQ * DMODEL],  g_att_l[MQ * DMODEL];
__device__ __nv_bfloat16 g_h1_h[MST * DMODEL],  g_h1_l[MST * DMODEL];
__device__ __nv_bfloat16 g_f1_h[MST * FFND],    g_f1_l[MST * FFND];
__device__ __nv_bfloat16 g_yin_h[2048 * DMODEL], g_yin_l[2048 * DMODEL];

// bf16 hi/lo weights
__device__ __nv_bfloat16 g_wq_h[8 * DMODEL * DMODEL], g_wq_l[8 * DMODEL * DMODEL];
__device__ __nv_bfloat16 g_wk_h[8 * DMODEL * DMODEL], g_wk_l[8 * DMODEL * DMODEL];
__device__ __nv_bfloat16 g_wv_h[8 * DMODEL * DMODEL], g_wv_l[8 * DMODEL * DMODEL];
__device__ __nv_bfloat16 g_wo_h[8 * DMODEL * DMODEL], g_wo_l[8 * DMODEL * DMODEL];
__device__ __nv_bfloat16 g_w1_h[8 * DMODEL * FFND],   g_w1_l[8 * DMODEL * FFND];
__device__ __nv_bfloat16 g_w2_h[8 * FFND * DMODEL],   g_w2_l[8 * FFND * DMODEL];
__device__ __nv_bfloat16 g_wout_h[DMODEL * OUTD],     g_wout_l[DMODEL * OUTD];

// ---------------------------------------------------------------------------
// split helpers
// ---------------------------------------------------------------------------
__device__ __forceinline__ void split1(float v, __nv_bfloat16& h, __nv_bfloat16& l) {
    h = __float2bfloat16(v);
    l = __float2bfloat16(v - __bfloat162float(h));
}

__device__ __forceinline__ void split_store4(float4 o, __nv_bfloat16* hi,
                                             __nv_bfloat16* lo, size_t idx) {
    __nv_bfloat16 h0, h1, h2, h3, l0, l1, l2, l3;
    split1(o.x, h0, l0); split1(o.y, h1, l1);
    split1(o.z, h2, l2); split1(o.w, h3, l3);
    *(__nv_bfloat162*)&hi[idx]     = __halves2bfloat162(h0, h1);
    *(__nv_bfloat162*)&hi[idx + 2] = __halves2bfloat162(h2, h3);
    *(__nv_bfloat162*)&lo[idx]     = __halves2bfloat162(l0, l1);
    *(__nv_bfloat162*)&lo[idx + 2] = __halves2bfloat162(l2, l3);
}

// plain fp32 -> hi/lo convert (n multiple of 4)
__global__ void cvt_kernel(const float* __restrict__ src, __nv_bfloat16* __restrict__ hi,
                           __nv_bfloat16* __restrict__ lo, int n4) {
    int i = blockIdx.x * blockDim.x + threadIdx.x;
    if (i >= n4) return;
    float4 v = *(const float4*)&src[(size_t)i * 4];
    split_store4(v, hi, lo, (size_t)i * 4);
}

// fp32 + colbias, relu -> hi/lo (for FFN1 output). N power of two.
__global__ void cvt_bias_relu_kernel(const float* __restrict__ src,
                                     const float* __restrict__ bias,
                                     __nv_bfloat16* __restrict__ hi,
                                     __nv_bfloat16* __restrict__ lo, int n4, int Nmask) {
    int i = blockIdx.x * blockDim.x + threadIdx.x;
    if (i >= n4) return;
    size_t base = (size_t)i * 4;
    int col = (int)(base & (size_t)Nmask);
    float4 v = *(const float4*)&src[base];
    float4 b = *(const float4*)&bias[col];
    v.x = fmaxf(v.x + b.x, 0.f);
    v.y = fmaxf(v.y + b.y, 0.f);
    v.z = fmaxf(v.z + b.z, 0.f);
    v.w = fmaxf(v.w + b.w, 0.f);
    split_store4(v, hi, lo, base);
}

// ---------------------------------------------------------------------------
// small utility kernels
// ---------------------------------------------------------------------------
__global__ void inproj_kernel(const float* __restrict__ inp,
                              const float* __restrict__ w,
                              float* __restrict__ xout) {
    int t = blockIdx.x, b = blockIdx.y;
    __shared__ float sh[80];
    int tid = threadIdx.x;
    if (tid < 80) sh[tid] = inp[((size_t)b * 1040 + t) * 80 + tid];
    __syncthreads();
    float s = 0.f;
#pragma unroll 16
    for (int k = 0; k < 80; k++) s += sh[k] * w[k * 128 + tid];
    xout[(((size_t)(t >> 2)) * NB + b) * DMODEL + (t & 3) * 128 + tid] = s;
}

__global__ void state_init_kernel(const float* __restrict__ x, float* __restrict__ st) {
    int i = blockIdx.x * blockDim.x + threadIdx.x;
    if (i >= STROWS * NB * DMODEL) return;
    int d = i & 511;
    int b = (i >> 9) & 7;
    int r = i >> 12;
    int src = (r < 64) ? (((r >> 2) + 1) * 16 + (r & 3)) : (r - 64);
    st[i] = x[((size_t)src * NB + b) * DMODEL + d];
}

// initial mems -> kin_cvt rows [0,15)
__global__ void mems0_kernel(const float* __restrict__ x,
                             __nv_bfloat16* __restrict__ kh, __nv_bfloat16* __restrict__ kl) {
    int i = blockIdx.x * blockDim.x + threadIdx.x;
    if (i >= NMEMS * NB * DMODEL) return;
    int d = i & 511;
    int b = (i >> 9) & 7;
    int s = i >> 12;
    float acc = 0.f;
    size_t base = ((size_t)(s * 16) * NB + b) * DMODEL + d;
    for (int t = 0; t < 16; t++) acc += x[base + (size_t)t * NB * DMODEL];
    acc *= (1.0f / 16.0f);
    split1(acc, kh[i], kl[i]);
}

// summary -> qin_cvt rows 320..335
__global__ void summary_kernel(const float* __restrict__ qin,
                               __nv_bfloat16* __restrict__ qh, __nv_bfloat16* __restrict__ ql) {
    int i = blockIdx.x * blockDim.x + threadIdx.x;
    if (i >= NSEG * NB * DMODEL) return;
    int d = i & 511;
    int b = (i >> 9) & 7;
    int s = i >> 12;
    float acc = 0.f;
    size_t base = ((size_t)(64 + s * 16) * NB + b) * DMODEL + d;
    for (int t = 0; t < 16; t++) acc += qin[base + (size_t)t * NB * DMODEL];
    acc *= (1.0f / 16.0f);
    size_t o = (size_t)STROWS * NB * DMODEL + i;
    split1(acc, qh[o], ql[o]);
}

// new mems = tanh(out rows 320..334 + bo) -> kin_cvt rows [0,15)
__global__ void mems_tanh_kernel(const float* __restrict__ out, const float* __restrict__ bo,
                                 __nv_bfloat16* __restrict__ kh, __nv_bfloat16* __restrict__ kl) {
    int i = blockIdx.x * blockDim.x + threadIdx.x;
    if (i >= NMEMS * NB * DMODEL) return;
    float v = tanhf(out[(size_t)STROWS * NB * DMODEL + i] + bo[i & 511]);
    split1(v, kh[i], kl[i]);
}

// yin hi/lo[(b*256+t)*512+d] = state[(64+t)*8+b, d]
__global__ void ytrans_kernel(const float* __restrict__ st,
                              __nv_bfloat16* __restrict__ yh, __nv_bfloat16* __restrict__ yl) {
    int i = blockIdx.x * blockDim.x + threadIdx.x;
    if (i >= 2048 * DMODEL) return;
    int d = i & 511;
    int m = i >> 9;
    int b = m >> 8;
    int t = m & 255;
    float v = st[((size_t)(64 + t) * NB + b) * DMODEL + d];
    split1(v, yh[i], yl[i]);
}

__global__ void lr_kernel(const int* __restrict__ lengths, float* __restrict__ out) {
    int b = threadIdx.x;
    if (b < 8) out[8u * 256u * 1024u + b] = (float)(lengths[b] >> 2);
}

// ---------------------------------------------------------------------------
// LayerNorm: v = in + colbias + addin ; optional pre-LN sum out, fp32 LN out,
// and up to two bf16 hi/lo LN outs.
// ---------------------------------------------------------------------------
template <int N>
__global__ __launch_bounds__(128) void ln4_kernel(const float* __restrict__ in,
                                                  const float* __restrict__ colbias,
                                                  const float* __restrict__ addin,
                                                  float* __restrict__ outsum,
                                                  float* __restrict__ outln,
                                                  __nv_bfloat16* __restrict__ oh1,
                                                  __nv_bfloat16* __restrict__ ol1,
                                                  __nv_bfloat16* __restrict__ oh2,
                                                  __nv_bfloat16* __restrict__ ol2,
                                                  const float* __restrict__ g,
                                                  const float* __restrict__ be) {
    constexpr int NV = N / 512;
    __shared__ float red[4];
    __shared__ float stat[2];
    int row = blockIdx.x, tid = threadIdx.x;
    size_t base = (size_t)row * N;
    float4 v[NV];
    float s = 0.f;
#pragma unroll
    for (int i = 0; i < NV; i++) {
        int c = (i * 128 + tid) * 4;
        float4 a = *(const float4*)&in[base + c];
        if (colbias) {
            float4 cb = *(const float4*)&colbias[c];
            a.x += cb.x; a.y += cb.y; a.z += cb.z; a.w += cb.w;
        }
        if (addin) {
            float4 r2 = *(const float4*)&addin[base + c];
            a.x += r2.x; a.y += r2.y; a.z += r2.z; a.w += r2.w;
        }
        v[i] = a;
        s += a.x + a.y + a.z + a.w;
    }
    for (int o = 16; o; o >>= 1) s += __shfl_xor_sync(0xffffffffu, s, o);
    if ((tid & 31) == 0) red[tid >> 5] = s;
    __syncthreads();
    if (tid == 0) stat[0] = (red[0] + red[1] + red[2] + red[3]) * (1.0f / N);
    __syncthreads();
    float mean = stat[0];
    float vs = 0.f;
#pragma unroll
    for (int i = 0; i < NV; i++) {
        float dx = v[i].x - mean, dy = v[i].y - mean, dz = v[i].z - mean, dw = v[i].w - mean;
        vs += dx * dx + dy * dy + dz * dz + dw * dw;
    }
    for (int o = 16; o; o >>= 1) vs += __shfl_xor_sync(0xffffffffu, vs, o);
    if ((tid & 31) == 0) red[tid >> 5] = vs;
    __syncthreads();
    if (tid == 0) stat[1] = rsqrtf((red[0] + red[1] + red[2] + red[3]) * (1.0f / N) + 1e-5f);
    __syncthreads();
    float rstd = stat[1];
#pragma unroll
    for (int i = 0; i < NV; i++) {
        int c = (i * 128 + tid) * 4;
        if (outsum) *(float4*)&outsum[base + c] = v[i];
        float4 gv = *(const float4*)&g[c];
        float4 bv = *(const float4*)&be[c];
        float4 o;
        o.x = (v[i].x - mean) * rstd * gv.x + bv.x;
        o.y = (v[i].y - mean) * rstd * gv.y + bv.y;
        o.z = (v[i].z - mean) * rstd * gv.z + bv.z;
        o.w = (v[i].w - mean) * rstd * gv.w + bv.w;
        if (outln) *(float4*)&outln[base + c] = o;
        if (oh1) split_store4(o, oh1, ol1, base + c);
        if (oh2) split_store4(o, oh2, ol2, base + c);
    }
}

// ---------------------------------------------------------------------------
// bf16x3 tensor-core GEMM: C = Ah@Bh + Al@Bh + Ah@Bl   (fp32 accumulate)
// A: [M,K] row-major bf16 (hi/lo). B: [K,N] row-major bf16 (hi/lo).
// Tile 128x128x32, 256 threads (8 warps, 2x4 warp grid, 64x32 warp tile).
// M, K multiples of 32 with M multiple of 128; N multiple of 128.
// ---------------------------------------------------------------------------
__device__ __forceinline__ void bgemm3_body(const __nv_bfloat16* __restrict__ Ah,
                                            const __nv_bfloat16* __restrict__ Al,
                                            const __nv_bfloat16* __restrict__ Bh,
                                            const __nv_bfloat16* __restrict__ Bl,
                                            float* __restrict__ C,
                                            int M, int N, int K,
                                            __nv_bfloat16* sAp, __nv_bfloat16* sBp) {
    constexpr int LDA = 40;    // sA row stride (elems)
    constexpr int LDB = 136;   // sB row stride (elems)
    int tid = threadIdx.x;
    int wid = tid >> 5, wm = wid >> 2, wn = wid & 3;
    size_t row0 = (size_t)blockIdx.y * 128;
    size_t col0 = (size_t)blockIdx.x * 128;

    const __nv_bfloat16* Ap[3] = {Ah, Al, Ah};
    const __nv_bfloat16* Bp[3] = {Bh, Bh, Bl};

    wmma::fragment<wmma::accumulator, 16, 16, 16, float> cf[4][2];
#pragma unroll
    for (int i = 0; i < 4; i++)
#pragma unroll
        for (int j = 0; j < 2; j++) wmma::fill_fragment(cf[i][j], 0.f);

    int id0 = tid, id1 = tid + 256;
    int Kd = K >> 5;
    int total = 3 * Kd;

    // preload tile 0
    uint4 a0 = *(const uint4*)(Ap[0] + (row0 + (id0 >> 2)) * K + (id0 & 3) * 8);
    uint4 a1 = *(const uint4*)(Ap[0] + (row0 + (id1 >> 2)) * K + (id1 & 3) * 8);
    uint4 b0 = *(const uint4*)(Bp[0] + (size_t)(id0 >> 4) * N + col0 + (id0 & 15) * 8);
    uint4 b1 = *(const uint4*)(Bp[0] + (size_t)(id1 >> 4) * N + col0 + (id1 & 15) * 8);
    *(uint4*)&sAp[(id0 >> 2) * LDA + (id0 & 3) * 8] = a0;
    *(uint4*)&sAp[(id1 >> 2) * LDA + (id1 & 3) * 8] = a1;
    *(uint4*)&sBp[(id0 >> 4) * LDB + (id0 & 15) * 8] = b0;
    *(uint4*)&sBp[(id1 >> 4) * LDB + (id1 & 15) * 8] = b1;
    __syncthreads();

    int buf = 0;
    for (int it = 0; it < total; it++) {
        if (it + 1 < total) {
            int p = (it + 1) / Kd;
            int k0 = ((it + 1) % Kd) << 5;
            a0 = *(const uint4*)(Ap[p] + (row0 + (id0 >> 2)) * K + k0 + (id0 & 3) * 8);
            a1 = *(const uint4*)(Ap[p] + (row0 + (id1 >> 2)) * K + k0 + (id1 & 3) * 8);
            b0 = *(const uint4*)(Bp[p] + (size_t)(k0 + (id0 >> 4)) * N + col0 + (id0 & 15) * 8);
            b1 = *(const uint4*)(Bp[p] + (size_t)(k0 + (id1 >> 4)) * N + col0 + (id1 & 15) * 8);
        }
        const __nv_bfloat16* a_ = sAp + buf * (128 * LDA);
        const __nv_bfloat16* b_ = sBp + buf * (32 * LDB);
#pragma unroll
        for (int ks = 0; ks < 2; ks++) {
            wmma::fragment<wmma::matrix_a, 16, 16, 16, __nv_bfloat16, wmma::row_major> af[4];
            wmma::fragment<wmma::matrix_b, 16, 16, 16, __nv_bfloat16, wmma::row_major> bf[2];
#pragma unroll
            for (int i = 0; i < 4; i++)
                wmma::load_matrix_sync(af[i], a_ + (wm * 64 + i * 16) * LDA + ks * 16, LDA);
#pragma unroll
            for (int j = 0; j < 2; j++)
                wmma::load_matrix_sync(bf[j], b_ + (ks * 16) * LDB + wn * 32 + j * 16, LDB);
#pragma unroll
            for (int i = 0; i < 4; i++)
#pragma unroll
                for (int j = 0; j < 2; j++)
                    wmma::mma_sync(cf[i][j], af[i], bf[j], cf[i][j]);
        }
        if (it + 1 < total) {
            int nb = buf ^ 1;
            __nv_bfloat16* dA = sAp + nb * (128 * LDA);
            __nv_bfloat16* dB = sBp + nb * (32 * LDB);
            *(uint4*)&dA[(id0 >> 2) * LDA + (id0 & 3) * 8] = a0;
            *(uint4*)&dA[(id1 >> 2) * LDA + (id1 & 3) * 8] = a1;
            *(uint4*)&dB[(id0 >> 4) * LDB + (id0 & 15) * 8] = b0;
            *(uint4*)&dB[(id1 >> 4) * LDB + (id1 & 15) * 8] = b1;
            __syncthreads();
            buf = nb;
        }
    }
#pragma unroll
    for (int i = 0; i < 4; i++)
#pragma unroll
        for (int j = 0; j < 2; j++)
            wmma::store_matrix_sync(C + (row0 + wm * 64 + i * 16) * N + col0 + wn * 32 + j * 16,
                                    cf[i][j], N, wmma::mem_row_major);
}

__global__ __launch_bounds__(256) void bgemm3(const __nv_bfloat16* Ah, const __nv_bfloat16* Al,
                                              const __nv_bfloat16* Bh, const __nv_bfloat16* Bl,
                                              float* C, int M, int N, int K) {
    __shared__ __align__(32) __nv_bfloat16 sA[2 * 128 * 40];
    __shared__ __align__(32) __nv_bfloat16 sB[2 * 32 * 136];
    bgemm3_body(Ah, Al, Bh, Bl, C, M, N, K, sA, sB);
}

// fused QKV: z selects which GEMM
__global__ __launch_bounds__(256) void bgemm3_qkv(
    const __nv_bfloat16* qh, const __nv_bfloat16* ql,
    const __nv_bfloat16* kh, const __nv_bfloat16* kl,
    const __nv_bfloat16* wqh, const __nv_bfloat16* wql,
    const __nv_bfloat16* wkh, const __nv_bfloat16* wkl,
    const __nv_bfloat16* wvh, const __nv_bfloat16* wvl,
    float* q, float* k, float* v) {
    __shared__ __align__(32) __nv_bfloat16 sA[2 * 128 * 40];
    __shared__ __align__(32) __nv_bfloat16 sB[2 * 32 * 136];
    int z = blockIdx.z;
    const __nv_bfloat16* Ah = (z == 0) ? qh : kh;
    const __nv_bfloat16* Al = (z == 0) ? ql : kl;
    const __nv_bfloat16* Bh = (z == 0) ? wqh : (z == 1) ? wkh : wvh;
    const __nv_bfloat16* Bl = (z == 0) ? wql : (z == 1) ? wkl : wvl;
    float* C = (z == 0) ? q : (z == 1) ? k : v;
    bgemm3_body(Ah, Al, Bh, Bl, C, 2688, DMODEL, DMODEL, sA, sB);
}

// ---------------------------------------------------------------------------
// Attention mask (static structure)
// ---------------------------------------------------------------------------
__device__ __forceinline__ bool attn_allowed(int qrow, int kc) {
    int i, typ;
    if (qrow < 64) { i = qrow >> 2; typ = 0; }
    else if (qrow < 320) { i = (qrow - 64) >> 4; typ = 1; }
    else { i = qrow - 320; typ = 2; }
    if (kc < 15) {
        if (typ == 2) return false;
        int ms = i - 4; if (ms < 0) ms = 0;
        return (kc >= ms) && (kc < i);
    } else if (kc < 79) {
        int c = kc - 15;
        return (c >> 2) == i;
    } else {
        int c = kc - 79;
        int ss = i * 16 - 32; if (ss < 0) ss = 0;
        int se = i * 16 + 16; if (se > 256) se = 256;
        return (c >= ss) && (c < se);
    }
}

#define FMA2(d, a, b) asm("fma.rn.f32x2 %0, %1, %2, %0;" : "+l"(d) : "l"(a), "l"(b))
#define PACK2(d, x)   asm("mov.b64 %0, {%1, %1};" : "=l"(d) : "f"(x))

// Fused attention with bias add on loads. block = (qtile16, head, batch).
__global__ __launch_bounds__(128) void attn_kernel(const float* __restrict__ Qb,
                                                   const float* __restrict__ Kb,
                                                   const float* __restrict__ Vb,
                                                   const float* __restrict__ bq,
                                                   const float* __restrict__ bk,
                                                   const float* __restrict__ bv,
                                                   const int* __restrict__ lengths,
                                                   float* __restrict__ Ob) {
    __shared__ float qs[16][66];
    __shared__ float sc[16][336];
    __shared__ float ch[32][66];
    __shared__ float rowsum[16];
    int b = blockIdx.z, h = blockIdx.y, qt = blockIdx.x;
    int tid = threadIdx.x;

    int lrb = lengths[b] >> 2;
    int maxlr = 0;
#pragma unroll
    for (int i = 0; i < 8; i++) {
        int v = lengths[i] >> 2;
        maxlr = max(maxlr, v);
    }
    int klen = 335 - (maxlr - lrb);

    for (int i = tid; i < 16 * 64; i += 128) {
        int r = i >> 6, d = i & 63;
        qs[r][d] = (Qb[(((size_t)(qt * 16 + r)) * NB + b) * DMODEL + h * 64 + d]
                    + bq[h * 64 + d]) * 0.125f;
    }
    __syncthreads();

    int r = tid >> 3;
    int cg = (tid & 7) * 4;
    int qrow = qt * 16 + r;

    // ---- scores ----
    for (int kc0 = 0; kc0 < KROWS; kc0 += 32) {
        int kcnt = min(32, KROWS - kc0);
        for (int i = tid; i < kcnt * 64; i += 128) {
            int kk = i >> 6, d = i & 63;
            ch[kk][d] = Kb[(((size_t)(kc0 + kk)) * NB + b) * DMODEL + h * 64 + d]
                        + bk[h * 64 + d];
        }
        __syncthreads();
        unsigned long long acc2[4] = {0ull, 0ull, 0ull, 0ull};
#pragma unroll
        for (int d = 0; d < 64; d += 2) {
            unsigned long long qp = *(const unsigned long long*)&qs[r][d];
            FMA2(acc2[0], qp, *(const unsigned long long*)&ch[cg + 0][d]);
            FMA2(acc2[1], qp, *(const unsigned long long*)&ch[cg + 1][d]);
            FMA2(acc2[2], qp, *(const unsigned long long*)&ch[cg + 2][d]);
            FMA2(acc2[3], qp, *(const unsigned long long*)&ch[cg + 3][d]);
        }
#pragma unroll
        for (int j = 0; j < 4; j++) {
            int kc = kc0 + cg + j;
            if (kc < KROWS) {
                float2 t = *(float2*)&acc2[j];
                float av = t.x + t.y;
                sc[r][kc] = (kc < klen && attn_allowed(qrow, kc)) ? av : -1e8f;
            }
        }
        __syncthreads();
    }

    // ---- softmax ----
    {
        int j = tid & 7;
        float m = -3.0e38f;
        for (int c = j; c < KROWS; c += 8) m = fmaxf(m, sc[r][c]);
        for (int o = 4; o; o >>= 1) m = fmaxf(m, __shfl_xor_sync(0xffffffffu, m, o));
        float s = 0.f;
        for (int c = j; c < KROWS; c += 8) {
            float e = __expf(sc[r][c] - m);
            sc[r][c] = e;
            s += e;
        }
        for (int o = 4; o; o >>= 1) s += __shfl_xor_sync(0xffffffffu, s, o);
        if (j == 0) rowsum[r] = s;
    }
    __syncthreads();

    // ---- probs @ V ----
    int dg = (tid & 7) * 8;
    unsigned long long acc[4] = {0ull, 0ull, 0ull, 0ull};
    for (int kc0 = 0; kc0 < KROWS; kc0 += 32) {
        int kcnt = min(32, KROWS - kc0);
        for (int i = tid; i < kcnt * 64; i += 128) {
            int kk = i >> 6, d = i & 63;
            ch[kk][d] = Vb[(((size_t)(kc0 + kk)) * NB + b) * DMODEL + h * 64 + d]
                        + bv[h * 64 + d];
        }
        __syncthreads();
        for (int kk = 0; kk < kcnt; kk++) {
            unsigned long long pd;
            PACK2(pd, sc[r][kc0 + kk]);
            FMA2(acc[0], pd, *(const unsigned long long*)&ch[kk][dg + 0]);
            FMA2(acc[1], pd, *(const unsigned long long*)&ch[kk][dg + 2]);
            FMA2(acc[2], pd, *(const unsigned long long*)&ch[kk][dg + 4]);
            FMA2(acc[3], pd, *(const unsigned long long*)&ch[kk][dg + 6]);
        }
        __syncthreads();
    }
    float inv = 1.0f / rowsum[r];
    float o[8];
#pragma unroll
    for (int u = 0; u < 4; u++) {
        float2 t = *(float2*)&acc[u];
        o[2 * u] = t.x * inv;
        o[2 * u + 1] = t.y * inv;
    }
    float* dst = &Ob[(((size_t)qrow) * NB + b) * DMODEL + h * 64 + dg];
    *(float4*)&dst[0] = make_float4(o[0], o[1], o[2], o[3]);
    *(float4*)&dst[4] = make_float4(o[4], o[5], o[6], o[7]);
}

// ---------------------------------------------------------------------------
// Host driver
// ---------------------------------------------------------------------------
extern "C" void kernel_launch(void* const* d_in, const int* in_sizes, int n_in,
                              void* d_out, int out_size) {
    const float* input   = (const float*)d_in[0];
    const int*   lengths = (const int*)d_in[1];
    const float* w_in    = (const float*)d_in[2];
    const float* ln_in_g = (const float*)d_in[3];
    const float* ln_in_b = (const float*)d_in[4];
    const float* wq      = (const float*)d_in[5];
    const float* bq      = (const float*)d_in[6];
    const float* wk      = (const float*)d_in[7];
    const float* bk      = (const float*)d_in[8];
    const float* wv      = (const float*)d_in[9];
    const float* bv      = (const float*)d_in[10];
    const float* wo      = (const float*)d_in[11];
    const float* bo      = (const float*)d_in[12];
    const float* ff_ln_g = (const float*)d_in[13];
    const float* ff_ln_b = (const float*)d_in[14];
    const float* w1      = (const float*)d_in[15];
    const float* b1      = (const float*)d_in[16];
    const float* w2      = (const float*)d_in[17];
    const float* b2      = (const float*)d_in[18];
    const float* ln_out_g = (const float*)d_in[19];
    const float* ln_out_b = (const float*)d_in[20];
    const float* w_out   = (const float*)d_in[21];
    const float* b_out   = (const float*)d_in[22];
    const float* lng     = (const float*)d_in[23];
    const float* lnb     = (const float*)d_in[24];
    float* out = (float*)d_out;

    float *px, *pstate, *pstate2, *pqin, *pq, *pk, *pv, *patt, *pout2, *pf1r, *pf2r, *pyt;
    cudaGetSymbolAddress((void**)&px, g_x);
    cudaGetSymbolAddress((void**)&pstate, g_state);
    cudaGetSymbolAddress((void**)&pstate2, g_state2);
    cudaGetSymbolAddress((void**)&pqin, g_qin);
    cudaGetSymbolAddress((void**)&pq, g_q);
    cudaGetSymbolAddress((void**)&pk, g_k);
    cudaGetSymbolAddress((void**)&pv, g_v);
    cudaGetSymbolAddress((void**)&patt, g_att);
    cudaGetSymbolAddress((void**)&pout2, g_out);
    cudaGetSymbolAddress((void**)&pf1r, g_f1raw);
    cudaGetSymbolAddress((void**)&pf2r, g_f2raw);
    cudaGetSymbolAddress((void**)&pyt, g_yt);

    __nv_bfloat16 *qinh, *qinl, *kinh, *kinl, *atth, *attl, *h1h, *h1l, *f1h, *f1l, *yinh, *yinl;
    cudaGetSymbolAddress((void**)&qinh, g_qin_h); cudaGetSymbolAddress((void**)&qinl, g_qin_l);
    cudaGetSymbolAddress((void**)&kinh, g_kin_h); cudaGetSymbolAddress((void**)&kinl, g_kin_l);
    cudaGetSymbolAddress((void**)&atth, g_att_h); cudaGetSymbolAddress((void**)&attl, g_att_l);
    cudaGetSymbolAddress((void**)&h1h, g_h1_h);   cudaGetSymbolAddress((void**)&h1l, g_h1_l);
    cudaGetSymbolAddress((void**)&f1h, g_f1_h);   cudaGetSymbolAddress((void**)&f1l, g_f1_l);
    cudaGetSymbolAddress((void**)&yinh, g_yin_h); cudaGetSymbolAddress((void**)&yinl, g_yin_l);

    __nv_bfloat16 *wqh, *wql, *wkh, *wkl, *wvh, *wvl, *woh, *wol, *w1h, *w1l, *w2h, *w2l, *wouth, *woutl;
    cudaGetSymbolAddress((void**)&wqh, g_wq_h);  cudaGetSymbolAddress((void**)&wql, g_wq_l);
    cudaGetSymbolAddress((void**)&wkh, g_wk_h);  cudaGetSymbolAddress((void**)&wkl, g_wk_l);
    cudaGetSymbolAddress((void**)&wvh, g_wv_h);  cudaGetSymbolAddress((void**)&wvl, g_wv_l);
    cudaGetSymbolAddress((void**)&woh, g_wo_h);  cudaGetSymbolAddress((void**)&wol, g_wo_l);
    cudaGetSymbolAddress((void**)&w1h, g_w1_h);  cudaGetSymbolAddress((void**)&w1l, g_w1_l);
    cudaGetSymbolAddress((void**)&w2h, g_w2_h);  cudaGetSymbolAddress((void**)&w2l, g_w2_l);
    cudaGetSymbolAddress((void**)&wouth, g_wout_h); cudaGetSymbolAddress((void**)&woutl, g_wout_l);

    // weight conversion (deterministic, same every call)
    const int WQN = 8 * DMODEL * DMODEL;      // 2.1M
    const int W1N = 8 * DMODEL * FFND;        // 8.4M
    cvt_kernel<<<(WQN / 4 + 255) / 256, 256>>>(wq, wqh, wql, WQN / 4);
    cvt_kernel<<<(WQN / 4 + 255) / 256, 256>>>(wk, wkh, wkl, WQN / 4);
    cvt_kernel<<<(WQN / 4 + 255) / 256, 256>>>(wv, wvh, wvl, WQN / 4);
    cvt_kernel<<<(WQN / 4 + 255) / 256, 256>>>(wo, woh, wol, WQN / 4);
    cvt_kernel<<<(W1N / 4 + 255) / 256, 256>>>(w1, w1h, w1l, W1N / 4);
    cvt_kernel<<<(W1N / 4 + 255) / 256, 256>>>(w2, w2h, w2l, W1N / 4);
    cvt_kernel<<<(DMODEL * OUTD / 4 + 255) / 256, 256>>>(w_out, wouth, woutl, DMODEL * OUTD / 4);

    inproj_kernel<<<dim3(1040, 8), 128>>>(input, w_in, px);
    state_init_kernel<<<(STROWS * NB * DMODEL + 255) / 256, 256>>>(px, pstate);
    mems0_kernel<<<(NMEMS * NB * DMODEL + 255) / 256, 256>>>(px, kinh, kinl);

    const size_t WS = (size_t)DMODEL * DMODEL;
    const size_t W1S = (size_t)DMODEL * FFND;
    const size_t KIN_OFF = (size_t)NMEMS * NB * DMODEL;

    for (int l = 0; l < 8; l++) {
        // LN1: state -> qin fp32 (summary input) + qin_cvt + kin_cvt[15..]
        ln4_kernel<512><<<STROWS * NB, 128>>>(pstate, nullptr, nullptr, nullptr, pqin,
                                              qinh, qinl, kinh + KIN_OFF, kinl + KIN_OFF,
                                              ln_in_g + l * DMODEL, ln_in_b + l * DMODEL);
        // summary -> qin_cvt rows 320..335
        summary_kernel<<<(NSEG * NB * DMODEL + 255) / 256, 256>>>(pqin, qinh, qinl);
        // fused QKV (252 CTAs)
        bgemm3_qkv<<<dim3(4, 21, 3), 256>>>(qinh, qinl, kinh, kinl,
                                            wqh + l * WS, wql + l * WS,
                                            wkh + l * WS, wkl + l * WS,
                                            wvh + l * WS, wvl + l * WS,
                                            pq, pk, pv);
        attn_kernel<<<dim3(21, 8, 8), 128>>>(pq, pk, pv,
                                             bq + l * DMODEL, bk + l * DMODEL, bv + l * DMODEL,
                                             lengths, patt);
        cvt_kernel<<<(MQ * DMODEL / 4 + 255) / 256, 256>>>(patt, atth, attl, MQ * DMODEL / 4);
        bgemm3<<<dim3(4, 21), 256>>>(atth, attl, woh + l * WS, wol + l * WS,
                                     pout2, MQ, DMODEL, DMODEL);
        mems_tanh_kernel<<<(NMEMS * NB * DMODEL + 255) / 256, 256>>>(pout2, bo + l * DMODEL,
                                                                     kinh, kinl);
        // res = out + bo + state; state2 = res; h1 = LN(res) -> hi/lo
        ln4_kernel<512><<<STROWS * NB, 128>>>(pout2, bo + l * DMODEL, pstate, pstate2, nullptr,
                                              h1h, h1l, nullptr, nullptr,
                                              ff_ln_g + l * DMODEL, ff_ln_b + l * DMODEL);
        bgemm3<<<dim3(16, 20), 256>>>(h1h, h1l, w1h + l * W1S, w1l + l * W1S,
                                      pf1r, MST, FFND, DMODEL);
        cvt_bias_relu_kernel<<<(MST * FFND / 4 + 255) / 256, 256>>>(pf1r, b1 + l * FFND,
                                                                    f1h, f1l, MST * FFND / 4,
                                                                    FFND - 1);
        bgemm3<<<dim3(4, 20), 256>>>(f1h, f1l, w2h + l * W1S, w2l + l * W1S,
                                     pf2r, MST, DMODEL, FFND);
        // state = LN(f2 + b2 + state2)
        ln4_kernel<512><<<STROWS * NB, 128>>>(pf2r, b2 + l * DMODEL, pstate2, nullptr, pstate,
                                              nullptr, nullptr, nullptr, nullptr,
                                              ln_out_g + l * DMODEL, ln_out_b + l * DMODEL);
    }

    ytrans_kernel<<<(2048 * DMODEL + 255) / 256, 256>>>(pstate, yinh, yinl);
    bgemm3<<<dim3(8, 16), 256>>>(yinh, yinl, wouth, woutl, pyt, 2048, OUTD, DMODEL);
    ln4_kernel<1024><<<2048, 128>>>(pyt, b_out, nullptr, nullptr, out,
                                    nullptr, nullptr, nullptr, nullptr, lng, lnb);

    if (out_size >= 8 * 256 * 1024 + 8) {
        lr_kernel<<<1, 8>>>(lengths, out);
    }
}

// round 14
// speedup vs baseline: 1.3038x; 1.3038x over previous
#include <cuda_runtime.h>
#include <cuda_bf16.h>
#include <mma.h>
#include <cstdint>
#include <cstddef>
using namespace nvcuda;

// ---------------------------------------------------------------------------
// Shapes: B=8 TIN=1040 IN=80 TRI=128 D=512 FFN=2048 L=8 OUT=1024
// H=8 DH=64 STRIDE=4 SEG=16 RC=4 LC=32 MAXMEM=4
// Tr=260 U=256 nseg=16 Rt=64 Q=336 K=335
// ---------------------------------------------------------------------------

#define NB 8
#define DMODEL 512
#define QROWS 336
#define KROWS 335
#define STROWS 320
#define TRROWS 260
#define NSEG 16
#define NMEMS 15
#define FFND 2048
#define OUTD 1024

#define MQ   (QROWS * NB)          // 2688 = 21*128
#define MKP  2688                  // kin padded rows
#define MST  (STROWS * NB)         // 2560 = 20*128

#define FMA2(d, a, b) asm("fma.rn.f32x2 %0, %1, %2, %0;" : "+l"(d) : "l"(a), "l"(b))
#define PACK2(d, x)   asm("mov.b64 %0, {%1, %1};" : "=l"(d) : "f"(x))

// ---------------------------------------------------------------------------
// fp32 scratch
// ---------------------------------------------------------------------------
__device__ float g_x[TRROWS * NB * DMODEL];
__device__ float g_state[STROWS * NB * DMODEL];
__device__ float g_state2[STROWS * NB * DMODEL];
__device__ float g_qin[QROWS * NB * DMODEL];
__device__ float g_q[MQ * DMODEL];
__device__ float g_k[MKP * DMODEL];
__device__ float g_v[MKP * DMODEL];
__device__ float g_out[MQ * DMODEL];
__device__ float g_f1raw[MST * FFND];
__device__ float g_f2raw[MST * DMODEL];
__device__ float g_yt[2048 * OUTD];

// bf16 hi/lo activations (zero-init pad rows stay zero)
__device__ __nv_bfloat16 g_qin_h[MQ * DMODEL],  g_qin_l[MQ * DMODEL];
__device__ __nv_bfloat16 g_kin_h[MKP * DMODEL], g_kin_l[MKP * DMODEL];
__device__ __nv_bfloat16 g_att_h[MQ * DMODEL],  g_att_l[MQ * DMODEL];
__device__ __nv_bfloat16 g_h1_h[MST * DMODEL],  g_h1_l[MST * DMODEL];
__device__ __nv_bfloat16 g_f1_h[MST * FFND],    g_f1_l[MST * FFND];
__device__ __nv_bfloat16 g_yin_h[2048 * DMODEL], g_yin_l[2048 * DMODEL];

// transposed bf16 hi/lo weights: Wt[n*K+k] = W[k*N+n]
__device__ __nv_bfloat16 g_wq_h[8 * DMODEL * DMODEL], g_wq_l[8 * DMODEL * DMODEL];
__device__ __nv_bfloat16 g_wk_h[8 * DMODEL * DMODEL], g_wk_l[8 * DMODEL * DMODEL];
__device__ __nv_bfloat16 g_wv_h[8 * DMODEL * DMODEL], g_wv_l[8 * DMODEL * DMODEL];
__device__ __nv_bfloat16 g_wo_h[8 * DMODEL * DMODEL], g_wo_l[8 * DMODEL * DMODEL];
__device__ __nv_bfloat16 g_w1_h[8 * DMODEL * FFND],   g_w1_l[8 * DMODEL * FFND];
__device__ __nv_bfloat16 g_w2_h[8 * FFND * DMODEL],   g_w2_l[8 * FFND * DMODEL];
__device__ __nv_bfloat16 g_wout_h[DMODEL * OUTD],     g_wout_l[DMODEL * OUTD];

// ---------------------------------------------------------------------------
// split helpers
// ---------------------------------------------------------------------------
__device__ __forceinline__ void split1(float v, __nv_bfloat16& h, __nv_bfloat16& l) {
    h = __float2bfloat16(v);
    l = __float2bfloat16(v - __bfloat162float(h));
}
__device__ __forceinline__ void split_store4(float4 o, __nv_bfloat16* hi,
                                             __nv_bfloat16* lo, size_t idx) {
    __nv_bfloat16 h0, h1, h2, h3, l0, l1, l2, l3;
    split1(o.x, h0, l0); split1(o.y, h1, l1);
    split1(o.z, h2, l2); split1(o.w, h3, l3);
    *(__nv_bfloat162*)&hi[idx]     = __halves2bfloat162(h0, h1);
    *(__nv_bfloat162*)&hi[idx + 2] = __halves2bfloat162(h2, h3);
    *(__nv_bfloat162*)&lo[idx]     = __halves2bfloat162(l0, l1);
    *(__nv_bfloat162*)&lo[idx + 2] = __halves2bfloat162(l2, l3);
}

__global__ void cvt_bias_relu_kernel(const float* __restrict__ src,
                                     const float* __restrict__ bias,
                                     __nv_bfloat16* __restrict__ hi,
                                     __nv_bfloat16* __restrict__ lo, int n4, int Nmask) {
    int i = blockIdx.x * blockDim.x + threadIdx.x;
    if (i >= n4) return;
    size_t base = (size_t)i * 4;
    int col = (int)(base & (size_t)Nmask);
    float4 v = *(const float4*)&src[base];
    float4 b = *(const float4*)&bias[col];
    v.x = fmaxf(v.x + b.x, 0.f);
    v.y = fmaxf(v.y + b.y, 0.f);
    v.z = fmaxf(v.z + b.z, 0.f);
    v.w = fmaxf(v.w + b.w, 0.f);
    split_store4(v, hi, lo, base);
}

// transpose + split: W[K,N] -> Wt hi/lo [N,K]
__global__ __launch_bounds__(256) void wtrans_kernel(const float* __restrict__ W,
                                                     __nv_bfloat16* __restrict__ Th,
                                                     __nv_bfloat16* __restrict__ Tl,
                                                     int K, int N) {
    __shared__ float t[32][33];
    int gn0 = blockIdx.x * 32, gk0 = blockIdx.y * 32;
    int tx = threadIdx.x, ty = threadIdx.y;   // 32 x 8
#pragma unroll
    for (int r = 0; r < 4; r++) {
        int k = gk0 + ty + r * 8;
        t[ty + r * 8][tx] = W[(size_t)k * N + gn0 + tx];
    }
    __syncthreads();
#pragma unroll
    for (int r = 0; r < 4; r++) {
        int n = gn0 + ty + r * 8;
        int k = gk0 + tx;
        float v = t[tx][ty + r * 8];
        __nv_bfloat16 h, l;
        split1(v, h, l);
        Th[(size_t)n * K + k] = h;
        Tl[(size_t)n * K + k] = l;
    }
}

// ---------------------------------------------------------------------------
// small utility kernels
// ---------------------------------------------------------------------------
__global__ void inproj_kernel(const float* __restrict__ inp,
                              const float* __restrict__ w,
                              float* __restrict__ xout) {
    int t = blockIdx.x, b = blockIdx.y;
    __shared__ float sh[80];
    int tid = threadIdx.x;
    if (tid < 80) sh[tid] = inp[((size_t)b * 1040 + t) * 80 + tid];
    __syncthreads();
    float s = 0.f;
#pragma unroll 16
    for (int k = 0; k < 80; k++) s += sh[k] * w[k * 128 + tid];
    xout[(((size_t)(t >> 2)) * NB + b) * DMODEL + (t & 3) * 128 + tid] = s;
}

__global__ void state_init_kernel(const float* __restrict__ x, float* __restrict__ st) {
    int i = blockIdx.x * blockDim.x + threadIdx.x;
    if (i >= STROWS * NB * DMODEL) return;
    int d = i & 511;
    int b = (i >> 9) & 7;
    int r = i >> 12;
    int src = (r < 64) ? (((r >> 2) + 1) * 16 + (r & 3)) : (r - 64);
    st[i] = x[((size_t)src * NB + b) * DMODEL + d];
}

__global__ void mems0_kernel(const float* __restrict__ x,
                             __nv_bfloat16* __restrict__ kh, __nv_bfloat16* __restrict__ kl) {
    int i = blockIdx.x * blockDim.x + threadIdx.x;
    if (i >= NMEMS * NB * DMODEL) return;
    int d = i & 511;
    int b = (i >> 9) & 7;
    int s = i >> 12;
    float acc = 0.f;
    size_t base = ((size_t)(s * 16) * NB + b) * DMODEL + d;
    for (int t = 0; t < 16; t++) acc += x[base + (size_t)t * NB * DMODEL];
    acc *= (1.0f / 16.0f);
    split1(acc, kh[i], kl[i]);
}

__global__ void summary_kernel(const float* __restrict__ qin,
                               __nv_bfloat16* __restrict__ qh, __nv_bfloat16* __restrict__ ql) {
    int i = blockIdx.x * blockDim.x + threadIdx.x;
    if (i >= NSEG * NB * DMODEL) return;
    int d = i & 511;
    int b = (i >> 9) & 7;
    int s = i >> 12;
    float acc = 0.f;
    size_t base = ((size_t)(64 + s * 16) * NB + b) * DMODEL + d;
    for (int t = 0; t < 16; t++) acc += qin[base + (size_t)t * NB * DMODEL];
    acc *= (1.0f / 16.0f);
    size_t o = (size_t)STROWS * NB * DMODEL + i;
    split1(acc, qh[o], ql[o]);
}

__global__ void mems_tanh_kernel(const float* __restrict__ out, const float* __restrict__ bo,
                                 __nv_bfloat16* __restrict__ kh, __nv_bfloat16* __restrict__ kl) {
    int i = blockIdx.x * blockDim.x + threadIdx.x;
    if (i >= NMEMS * NB * DMODEL) return;
    float v = tanhf(out[(size_t)STROWS * NB * DMODEL + i] + bo[i & 511]);
    split1(v, kh[i], kl[i]);
}

__global__ void ytrans_kernel(const float* __restrict__ st,
                              __nv_bfloat16* __restrict__ yh, __nv_bfloat16* __restrict__ yl) {
    int i = blockIdx.x * blockDim.x + threadIdx.x;
    if (i >= 2048 * DMODEL) return;
    int d = i & 511;
    int m = i >> 9;
    int b = m >> 8;
    int t = m & 255;
    float v = st[((size_t)(64 + t) * NB + b) * DMODEL + d];
    split1(v, yh[i], yl[i]);
}

__global__ void lr_kernel(const int* __restrict__ lengths, float* __restrict__ out) {
    int b = threadIdx.x;
    if (b < 8) out[8u * 256u * 1024u + b] = (float)(lengths[b] >> 2);
}

// ---------------------------------------------------------------------------
// LayerNorm
// ---------------------------------------------------------------------------
template <int N>
__global__ __launch_bounds__(128) void ln4_kernel(const float* __restrict__ in,
                                                  const float* __restrict__ colbias,
                                                  const float* __restrict__ addin,
                                                  float* __restrict__ outsum,
                                                  float* __restrict__ outln,
                                                  __nv_bfloat16* __restrict__ oh1,
                                                  __nv_bfloat16* __restrict__ ol1,
                                                  __nv_bfloat16* __restrict__ oh2,
                                                  __nv_bfloat16* __restrict__ ol2,
                                                  const float* __restrict__ g,
                                                  const float* __restrict__ be) {
    constexpr int NV = N / 512;
    __shared__ float red[4];
    __shared__ float stat[2];
    int row = blockIdx.x, tid = threadIdx.x;
    size_t base = (size_t)row * N;
    float4 v[NV];
    float s = 0.f;
#pragma unroll
    for (int i = 0; i < NV; i++) {
        int c = (i * 128 + tid) * 4;
        float4 a = *(const float4*)&in[base + c];
        if (colbias) {
            float4 cb = *(const float4*)&colbias[c];
            a.x += cb.x; a.y += cb.y; a.z += cb.z; a.w += cb.w;
        }
        if (addin) {
            float4 r2 = *(const float4*)&addin[base + c];
            a.x += r2.x; a.y += r2.y; a.z += r2.z; a.w += r2.w;
        }
        v[i] = a;
        s += a.x + a.y + a.z + a.w;
    }
    for (int o = 16; o; o >>= 1) s += __shfl_xor_sync(0xffffffffu, s, o);
    if ((tid & 31) == 0) red[tid >> 5] = s;
    __syncthreads();
    if (tid == 0) stat[0] = (red[0] + red[1] + red[2] + red[3]) * (1.0f / N);
    __syncthreads();
    float mean = stat[0];
    float vs = 0.f;
#pragma unroll
    for (int i = 0; i < NV; i++) {
        float dx = v[i].x - mean, dy = v[i].y - mean, dz = v[i].z - mean, dw = v[i].w - mean;
        vs += dx * dx + dy * dy + dz * dz + dw * dw;
    }
    for (int o = 16; o; o >>= 1) vs += __shfl_xor_sync(0xffffffffu, vs, o);
    if ((tid & 31) == 0) red[tid >> 5] = vs;
    __syncthreads();
    if (tid == 0) stat[1] = rsqrtf((red[0] + red[1] + red[2] + red[3]) * (1.0f / N) + 1e-5f);
    __syncthreads();
    float rstd = stat[1];
#pragma unroll
    for (int i = 0; i < NV; i++) {
        int c = (i * 128 + tid) * 4;
        if (outsum) *(float4*)&outsum[base + c] = v[i];
        float4 gv = *(const float4*)&g[c];
        float4 bv = *(const float4*)&be[c];
        float4 o;
        o.x = (v[i].x - mean) * rstd * gv.x + bv.x;
        o.y = (v[i].y - mean) * rstd * gv.y + bv.y;
        o.z = (v[i].z - mean) * rstd * gv.z + bv.z;
        o.w = (v[i].w - mean) * rstd * gv.w + bv.w;
        if (outln) *(float4*)&outln[base + c] = o;
        if (oh1) split_store4(o, oh1, ol1, base + c);
        if (oh2) split_store4(o, oh2, ol2, base + c);
    }
}

// ---------------------------------------------------------------------------
// WMMA bf16x3 GEMM v2: C[M,N] = Ah@BhT + Al@BhT + Ah@BlT (fp32 acc)
// A: [M,K] row-major bf16 hi/lo. Bt: [N,K] row-major bf16 hi/lo.
// CTA 128x128, 128 threads = 4 warps (2x2), warp tile 64x64 (4x4 frags).
// Both tiles stored [row][k] with ld=40 elems (80B, 16B-aligned,
// LDSM conflict-free). B consumed as col_major fragments.
// M%128==0, N%128==0, K%32==0.
// ---------------------------------------------------------------------------
#define GLD 40

__device__ __forceinline__ void bgemm_w_body(const __nv_bfloat16* __restrict__ Ah,
                                             const __nv_bfloat16* __restrict__ Al,
                                             const __nv_bfloat16* __restrict__ Bh,
                                             const __nv_bfloat16* __restrict__ Bl,
                                             float* __restrict__ C,
                                             int M, int N, int K) {
    __shared__ __align__(16) __nv_bfloat16 sA[2][128 * GLD];
    __shared__ __align__(16) __nv_bfloat16 sB[2][128 * GLD];
    int tid = threadIdx.x;
    int wid = tid >> 5;
    int wm = wid >> 1, wn = wid & 1;
    size_t row0 = (size_t)blockIdx.y * 128;
    size_t col0 = (size_t)blockIdx.x * 128;

    const __nv_bfloat16* Ap[3] = {Ah, Al, Ah};
    const __nv_bfloat16* Bp[3] = {Bh, Bh, Bl};

    wmma::fragment<wmma::accumulator, 16, 16, 16, float> acc[4][4];
#pragma unroll
    for (int i = 0; i < 4; i++)
#pragma unroll
        for (int j = 0; j < 4; j++) wmma::fill_fragment(acc[i][j], 0.f);

    int Kc = K >> 5;
    int total = 3 * Kc;

    uint4 a_st[4], b_st[4];
    // preload chunk 0
#pragma unroll
    for (int i = 0; i < 4; i++) {
        int id = tid + i * 128;
        a_st[i] = *(const uint4*)(Ap[0] + (row0 + (id >> 2)) * (size_t)K + (id & 3) * 8);
        b_st[i] = *(const uint4*)(Bp[0] + (col0 + (id >> 2)) * (size_t)K + (id & 3) * 8);
    }
#pragma unroll
    for (int i = 0; i < 4; i++) {
        int id = tid + i * 128;
        *(uint4*)&sA[0][(id >> 2) * GLD + (id & 3) * 8] = a_st[i];
        *(uint4*)&sB[0][(id >> 2) * GLD + (id & 3) * 8] = b_st[i];
    }
    __syncthreads();

    int buf = 0;
    for (int it = 0; it < total; it++) {
        if (it + 1 < total) {
            int p = (it + 1) / Kc;
            int k0 = ((it + 1) % Kc) << 5;
#pragma unroll
            for (int i = 0; i < 4; i++) {
                int id = tid + i * 128;
                a_st[i] = *(const uint4*)(Ap[p] + (row0 + (id >> 2)) * (size_t)K + k0 + (id & 3) * 8);
                b_st[i] = *(const uint4*)(Bp[p] + (col0 + (id >> 2)) * (size_t)K + k0 + (id & 3) * 8);
            }
        }
        const __nv_bfloat16* a_ = sA[buf];
        const __nv_bfloat16* b_ = sB[buf];
#pragma unroll
        for (int ks = 0; ks < 2; ks++) {
            wmma::fragment<wmma::matrix_a, 16, 16, 16, __nv_bfloat16, wmma::row_major> af[4];
            wmma::fragment<wmma::matrix_b, 16, 16, 16, __nv_bfloat16, wmma::col_major> bf[4];
#pragma unroll
            for (int i = 0; i < 4; i++)
                wmma::load_matrix_sync(af[i], a_ + (wm * 64 + i * 16) * GLD + ks * 16, GLD);
#pragma unroll
            for (int j = 0; j < 4; j++)
                wmma::load_matrix_sync(bf[j], b_ + (wn * 64 + j * 16) * GLD + ks * 16, GLD);
#pragma unroll
            for (int i = 0; i < 4; i++)
#pragma unroll
                for (int j = 0; j < 4; j++)
                    wmma::mma_sync(acc[i][j], af[i], bf[j], acc[i][j]);
        }
        if (it + 1 < total) {
            buf ^= 1;
#pragma unroll
            for (int i = 0; i < 4; i++) {
                int id = tid + i * 128;
                *(uint4*)&sA[buf][(id >> 2) * GLD + (id & 3) * 8] = a_st[i];
                *(uint4*)&sB[buf][(id >> 2) * GLD + (id & 3) * 8] = b_st[i];
            }
            __syncthreads();
        }
    }
#pragma unroll
    for (int i = 0; i < 4; i++)
#pragma unroll
        for (int j = 0; j < 4; j++)
            wmma::store_matrix_sync(C + (row0 + wm * 64 + i * 16) * N + col0 + wn * 64 + j * 16,
                                    acc[i][j], N, wmma::mem_row_major);
}

__global__ __launch_bounds__(128) void bgemm_w(const __nv_bfloat16* Ah, const __nv_bfloat16* Al,
                                               const __nv_bfloat16* Bh, const __nv_bfloat16* Bl,
                                               float* C, int M, int N, int K) {
    bgemm_w_body(Ah, Al, Bh, Bl, C, M, N, K);
}

__global__ __launch_bounds__(128) void bgemm_w_qkv(
    const __nv_bfloat16* qh, const __nv_bfloat16* ql,
    const __nv_bfloat16* kh, const __nv_bfloat16* kl,
    const __nv_bfloat16* wqh, const __nv_bfloat16* wql,
    const __nv_bfloat16* wkh, const __nv_bfloat16* wkl,
    const __nv_bfloat16* wvh, const __nv_bfloat16* wvl,
    float* q, float* k, float* v) {
    int z = blockIdx.z;
    const __nv_bfloat16* Ah = (z == 0) ? qh : kh;
    const __nv_bfloat16* Al = (z == 0) ? ql : kl;
    const __nv_bfloat16* Bh = (z == 0) ? wqh : (z == 1) ? wkh : wvh;
    const __nv_bfloat16* Bl = (z == 0) ? wql : (z == 1) ? wkl : wvl;
    float* C = (z == 0) ? q : (z == 1) ? k : v;
    bgemm_w_body(Ah, Al, Bh, Bl, C, 2688, DMODEL, DMODEL);
}

// ---------------------------------------------------------------------------
// Sparse attention. The static mask admits, for segment i:
//   mems  [max(i-4,0), i)                (<=4 keys, kc in [0,15))
//   rc    [15+4i, 15+4i+4)               (4 keys)
//   utt   [79+max(16i-32,0), 79+min(16i+16,256))   (<=48 keys)
// All 21 q rows of segment i (4 rc + 16 utt + 1 summary) share this superset;
// the summary row additionally masks the mems part. Padding: kc < klen[b].
// Block = (segment, head, batch), 128 threads, <=64 gathered keys.
// Writes hi/lo bf16 directly (feeds the Wo GEMM).
// ---------------------------------------------------------------------------
__global__ __launch_bounds__(128) void attn_sparse(const float* __restrict__ Qb,
                                                   const float* __restrict__ Kb,
                                                   const float* __restrict__ Vb,
                                                   const float* __restrict__ bq,
                                                   const float* __restrict__ bk,
                                                   const float* __restrict__ bv,
                                                   const int* __restrict__ lengths,
                                                   __nv_bfloat16* __restrict__ Oh,
                                                   __nv_bfloat16* __restrict__ Ol) {
    __shared__ float qs[21][66];
    __shared__ float kT[64][66];   // [d][j]
    __shared__ float vs[64][66];   // [j][d]
    __shared__ float sc[21][66];
    int i = blockIdx.x, h = blockIdx.y, b = blockIdx.z;
    int tid = threadIdx.x, lane = tid & 31, wid = tid >> 5;

    int nm = min(i, 4);
    int ms = i - nm;
    int ss = max(16 * i - 32, 0);
    int se = min(16 * i + 16, 256);
    int cnt = nm + 4 + (se - ss);

    int lrb = lengths[b] >> 2;
    int maxlr = 0;
#pragma unroll
    for (int t = 0; t < 8; t++) maxlr = max(maxlr, lengths[t] >> 2);
    int klen = 335 - (maxlr - lrb);

    // zero V (pad rows must be 0 so 0*garbage never produces NaN)
    for (int idx = tid; idx < 64 * 66; idx += 128) ((float*)vs)[idx] = 0.f;
    __syncthreads();

    // gather K (transposed) and V
    {
        int j = tid >> 1, half = tid & 1;
        if (j < cnt) {
            int kc = (j < nm) ? (ms + j)
                   : (j < nm + 4) ? (15 + 4 * i + (j - nm))
                   : (79 + ss + (j - nm - 4));
            const float* kr = Kb + ((size_t)kc * NB + b) * DMODEL + h * 64 + half * 32;
            const float* vr = Vb + ((size_t)kc * NB + b) * DMODEL + h * 64 + half * 32;
            const float* bkh = bk + h * 64 + half * 32;
            const float* bvh = bv + h * 64 + half * 32;
#pragma unroll
            for (int d = 0; d < 32; d++) {
                kT[half * 32 + d][j] = kr[d] + bkh[d];
                vs[j][half * 32 + d] = vr[d] + bvh[d];
            }
        }
    }
    // load Q (21 rows)
    for (int idx = tid; idx < 21 * 64; idx += 128) {
        int r = idx >> 6, d = idx & 63;
        int g = (r < 4) ? (4 * i + r) : (r < 20) ? (64 + 16 * i + (r - 4)) : (320 + i);
        qs[r][d] = (Qb[((size_t)g * NB + b) * DMODEL + h * 64 + d] + bq[h * 64 + d]) * 0.125f;
    }
    __syncthreads();

    // scores: warp handles a row, lane computes key pair (2*lane, 2*lane+1)
    for (int rp = 0; rp < 6; rp++) {
        int r = rp * 4 + wid;
        if (r < 21) {
            unsigned long long acc2 = 0ull;
#pragma unroll
            for (int d = 0; d < 64; d++) {
                unsigned long long qp;
                PACK2(qp, qs[r][d]);
                FMA2(acc2, qp, *(const unsigned long long*)&kT[d][2 * lane]);
            }
            float2 t = *(float2*)&acc2;
#pragma unroll
            for (int u = 0; u < 2; u++) {
                int j = 2 * lane + u;
                float dot = u ? t.y : t.x;
                bool ok = (j < cnt);
                if (ok) {
                    int kc = (j < nm) ? (ms + j)
                           : (j < nm + 4) ? (15 + 4 * i + (j - nm))
                           : (79 + ss + (j - nm - 4));
                    ok = (kc < klen) && !(r == 20 && j < nm);
                }
                sc[r][j] = ok ? dot : -1e8f;
            }
        }
    }
    __syncthreads();

    // softmax per row (normalized probs written back)
    for (int r = wid; r < 21; r += 4) {
        float a = sc[r][lane], c = sc[r][lane + 32];
        float m = fmaxf(a, c);
        for (int o = 16; o; o >>= 1) m = fmaxf(m, __shfl_xor_sync(0xffffffffu, m, o));
        float e1 = __expf(a - m), e2 = __expf(c - m);
        float s = e1 + e2;
        for (int o = 16; o; o >>= 1) s += __shfl_xor_sync(0xffffffffu, s, o);
        float inv = 1.0f / s;
        sc[r][lane] = e1 * inv;
        sc[r][lane + 32] = e2 * inv;
    }
    __syncthreads();

    // P @ V: warp per row, lane computes d pair; write hi/lo bf16
    for (int rp = 0; rp < 6; rp++) {
        int r = rp * 4 + wid;
        if (r < 21) {
            unsigned long long acc2 = 0ull;
#pragma unroll
            for (int j = 0; j < 64; j++) {
                unsigned long long pp;
                PACK2(pp, sc[r][j]);
                FMA2(acc2, pp, *(const unsigned long long*)&vs[j][2 * lane]);
            }
            float2 t = *(float2*)&acc2;
            int g = (r < 4) ? (4 * i + r) : (r < 20) ? (64 + 16 * i + (r - 4)) : (320 + i);
            size_t base = ((size_t)g * NB + b) * DMODEL + h * 64 + 2 * lane;
            __nv_bfloat16 h0, l0, h1, l1;
            split1(t.x, h0, l0);
            split1(t.y, h1, l1);
            *(__nv_bfloat162*)&Oh[base] = __halves2bfloat162(h0, h1);
            *(__nv_bfloat162*)&Ol[base] = __halves2bfloat162(l0, l1);
        }
    }
}

// ---------------------------------------------------------------------------
// Host driver
// ---------------------------------------------------------------------------
extern "C" void kernel_launch(void* const* d_in, const int* in_sizes, int n_in,
                              void* d_out, int out_size) {
    const float* input   = (const float*)d_in[0];
    const int*   lengths = (const int*)d_in[1];
    const float* w_in    = (const float*)d_in[2];
    const float* ln_in_g = (const float*)d_in[3];
    const float* ln_in_b = (const float*)d_in[4];
    const float* wq      = (const float*)d_in[5];
    const float* bq      = (const float*)d_in[6];
    const float* wk      = (const float*)d_in[7];
    const float* bk      = (const float*)d_in[8];
    const float* wv      = (const float*)d_in[9];
    const float* bv      = (const float*)d_in[10];
    const float* wo      = (const float*)d_in[11];
    const float* bo      = (const float*)d_in[12];
    const float* ff_ln_g = (const float*)d_in[13];
    const float* ff_ln_b = (const float*)d_in[14];
    const float* w1      = (const float*)d_in[15];
    const float* b1      = (const float*)d_in[16];
    const float* w2      = (const float*)d_in[17];
    const float* b2      = (const float*)d_in[18];
    const float* ln_out_g = (const float*)d_in[19];
    const float* ln_out_b = (const float*)d_in[20];
    const float* w_out   = (const float*)d_in[21];
    const float* b_out   = (const float*)d_in[22];
    const float* lng     = (const float*)d_in[23];
    const float* lnb     = (const float*)d_in[24];
    float* out = (float*)d_out;

    float *px, *pstate, *pstate2, *pqin, *pq, *pk, *pv, *pout2, *pf1r, *pf2r, *pyt;
    cudaGetSymbolAddress((void**)&px, g_x);
    cudaGetSymbolAddress((void**)&pstate, g_state);
    cudaGetSymbolAddress((void**)&pstate2, g_state2);
    cudaGetSymbolAddress((void**)&pqin, g_qin);
    cudaGetSymbolAddress((void**)&pq, g_q);
    cudaGetSymbolAddress((void**)&pk, g_k);
    cudaGetSymbolAddress((void**)&pv, g_v);
    cudaGetSymbolAddress((void**)&pout2, g_out);
    cudaGetSymbolAddress((void**)&pf1r, g_f1raw);
    cudaGetSymbolAddress((void**)&pf2r, g_f2raw);
    cudaGetSymbolAddress((void**)&pyt, g_yt);

    __nv_bfloat16 *qinh, *qinl, *kinh, *kinl, *atth, *attl, *h1h, *h1l, *f1h, *f1l, *yinh, *yinl;
    cudaGetSymbolAddress((void**)&qinh, g_qin_h); cudaGetSymbolAddress((void**)&qinl, g_qin_l);
    cudaGetSymbolAddress((void**)&kinh, g_kin_h); cudaGetSymbolAddress((void**)&kinl, g_kin_l);
    cudaGetSymbolAddress((void**)&atth, g_att_h); cudaGetSymbolAddress((void**)&attl, g_att_l);
    cudaGetSymbolAddress((void**)&h1h, g_h1_h);   cudaGetSymbolAddress((void**)&h1l, g_h1_l);
    cudaGetSymbolAddress((void**)&f1h, g_f1_h);   cudaGetSymbolAddress((void**)&f1l, g_f1_l);
    cudaGetSymbolAddress((void**)&yinh, g_yin_h); cudaGetSymbolAddress((void**)&yinl, g_yin_l);

    __nv_bfloat16 *wqh, *wql, *wkh, *wkl, *wvh, *wvl, *woh, *wol, *w1h, *w1l, *w2h, *w2l, *wouth, *woutl;
    cudaGetSymbolAddress((void**)&wqh, g_wq_h);  cudaGetSymbolAddress((void**)&wql, g_wq_l);
    cudaGetSymbolAddress((void**)&wkh, g_wk_h);  cudaGetSymbolAddress((void**)&wkl, g_wk_l);
    cudaGetSymbolAddress((void**)&wvh, g_wv_h);  cudaGetSymbolAddress((void**)&wvl, g_wv_l);
    cudaGetSymbolAddress((void**)&woh, g_wo_h);  cudaGetSymbolAddress((void**)&wol, g_wo_l);
    cudaGetSymbolAddress((void**)&w1h, g_w1_h);  cudaGetSymbolAddress((void**)&w1l, g_w1_l);
    cudaGetSymbolAddress((void**)&w2h, g_w2_h);  cudaGetSymbolAddress((void**)&w2l, g_w2_l);
    cudaGetSymbolAddress((void**)&wouth, g_wout_h); cudaGetSymbolAddress((void**)&woutl, g_wout_l);

    // weight transpose + split: W[K,N] -> Wt[N,K] hi/lo
    const size_t WS = (size_t)DMODEL * DMODEL;
    const size_t W1S = (size_t)DMODEL * FFND;
    dim3 tb(32, 8);
    for (int l = 0; l < 8; l++) {
        wtrans_kernel<<<dim3(DMODEL / 32, DMODEL / 32), tb>>>(wq + l * WS, wqh + l * WS, wql + l * WS, DMODEL, DMODEL);
        wtrans_kernel<<<dim3(DMODEL / 32, DMODEL / 32), tb>>>(wk + l * WS, wkh + l * WS, wkl + l * WS, DMODEL, DMODEL);
        wtrans_kernel<<<dim3(DMODEL / 32, DMODEL / 32), tb>>>(wv + l * WS, wvh + l * WS, wvl + l * WS, DMODEL, DMODEL);
        wtrans_kernel<<<dim3(DMODEL / 32, DMODEL / 32), tb>>>(wo + l * WS, woh + l * WS, wol + l * WS, DMODEL, DMODEL);
        wtrans_kernel<<<dim3(FFND / 32, DMODEL / 32), tb>>>(w1 + l * W1S, w1h + l * W1S, w1l + l * W1S, DMODEL, FFND);
        wtrans_kernel<<<dim3(DMODEL / 32, FFND / 32), tb>>>(w2 + l * W1S, w2h + l * W1S, w2l + l * W1S, FFND, DMODEL);
    }
    wtrans_kernel<<<dim3(OUTD / 32, DMODEL / 32), tb>>>(w_out, wouth, woutl, DMODEL, OUTD);

    inproj_kernel<<<dim3(1040, 8), 128>>>(input, w_in, px);
    state_init_kernel<<<(STROWS * NB * DMODEL + 255) / 256, 256>>>(px, pstate);
    mems0_kernel<<<(NMEMS * NB * DMODEL + 255) / 256, 256>>>(px, kinh, kinl);

    const size_t KIN_OFF = (size_t)NMEMS * NB * DMODEL;

    for (int l = 0; l < 8; l++) {
        ln4_kernel<512><<<STROWS * NB, 128>>>(pstate, nullptr, nullptr, nullptr, pqin,
                                              qinh, qinl, kinh + KIN_OFF, kinl + KIN_OFF,
                                              ln_in_g + l * DMODEL, ln_in_b + l * DMODEL);
        summary_kernel<<<(NSEG * NB * DMODEL + 255) / 256, 256>>>(pqin, qinh, qinl);
        bgemm_w_qkv<<<dim3(4, 21, 3), 128>>>(qinh, qinl, kinh, kinl,
                                             wqh + l * WS, wql + l * WS,
                                             wkh + l * WS, wkl + l * WS,
                                             wvh + l * WS, wvl + l * WS,
                                             pq, pk, pv);
        attn_sparse<<<dim3(16, 8, 8), 128>>>(pq, pk, pv,
                                             bq + l * DMODEL, bk + l * DMODEL, bv + l * DMODEL,
                                             lengths, atth, attl);
        bgemm_w<<<dim3(4, 21), 128>>>(atth, attl, woh + l * WS, wol + l * WS,
                                      pout2, MQ, DMODEL, DMODEL);
        mems_tanh_kernel<<<(NMEMS * NB * DMODEL + 255) / 256, 256>>>(pout2, bo + l * DMODEL,
                                                                     kinh, kinl);
        ln4_kernel<512><<<STROWS * NB, 128>>>(pout2, bo + l * DMODEL, pstate, pstate2, nullptr,
                                              h1h, h1l, nullptr, nullptr,
                                              ff_ln_g + l * DMODEL, ff_ln_b + l * DMODEL);
        bgemm_w<<<dim3(16, 20), 128>>>(h1h, h1l, w1h + l * W1S, w1l + l * W1S,
                                       pf1r, MST, FFND, DMODEL);
        cvt_bias_relu_kernel<<<(MST * FFND / 4 + 255) / 256, 256>>>(pf1r, b1 + l * FFND,
                                                                    f1h, f1l, MST * FFND / 4,
                                                                    FFND - 1);
        bgemm_w<<<dim3(4, 20), 128>>>(f1h, f1l, w2h + l * W1S, w2l + l * W1S,
                                      pf2r, MST, DMODEL, FFND);
        ln4_kernel<512><<<STROWS * NB, 128>>>(pf2r, b2 + l * DMODEL, pstate2, nullptr, pstate,
                                              nullptr, nullptr, nullptr, nullptr,
                                              ln_out_g + l * DMODEL, ln_out_b + l * DMODEL);
    }

    ytrans_kernel<<<(2048 * DMODEL + 255) / 256, 256>>>(pstate, yinh, yinl);
    bgemm_w<<<dim3(8, 16), 128>>>(yinh, yinl, wouth, woutl, pyt, 2048, OUTD, DMODEL);
    ln4_kernel<1024><<<2048, 128>>>(pyt, b_out, nullptr, nullptr, out,
                                    nullptr, nullptr, nullptr, nullptr, lng, lnb);

    if (out_size >= 8 * 256 * 1024 + 8) {
        lr_kernel<<<1, 8>>>(lengths, out);
    }
}

// round 17
// speedup vs baseline: 1.3603x; 1.0433x over previous
#include <cuda_runtime.h>
#include <cuda_bf16.h>
#include <mma.h>
#include <cstdint>
#include <cstddef>
using namespace nvcuda;

// ---------------------------------------------------------------------------
// Shapes: B=8 TIN=1040 IN=80 TRI=128 D=512 FFN=2048 L=8 OUT=1024
// H=8 DH=64 STRIDE=4 SEG=16 RC=4 LC=32 MAXMEM=4
// Tr=260 U=256 nseg=16 Rt=64 Q=336 K=335
// ---------------------------------------------------------------------------

#define NB 8
#define DMODEL 512
#define QROWS 336
#define KROWS 335
#define STROWS 320
#define TRROWS 260
#define NSEG 16
#define NMEMS 15
#define FFND 2048
#define OUTD 1024

#define MQ   (QROWS * NB)          // 2688 = 21*128
#define MKP  2688                  // kin padded rows
#define MST  (STROWS * NB)         // 2560 = 20*128

#define FMA2(d, a, b) asm("fma.rn.f32x2 %0, %1, %2, %0;" : "+l"(d) : "l"(a), "l"(b))
#define PACK2(d, x)   asm("mov.b64 %0, {%1, %1};" : "=l"(d) : "f"(x))

// ---------------------------------------------------------------------------
// fp32 scratch
// ---------------------------------------------------------------------------
__device__ float g_x[TRROWS * NB * DMODEL];
__device__ float g_state[STROWS * NB * DMODEL];
__device__ float g_state2[STROWS * NB * DMODEL];
__device__ float g_qin[QROWS * NB * DMODEL];
__device__ float g_q[MQ * DMODEL];
__device__ float g_k[MKP * DMODEL];
__device__ float g_v[MKP * DMODEL];
__device__ float g_out[MQ * DMODEL];
__device__ float g_f2raw[MST * DMODEL];
__device__ float g_yt[2048 * OUTD];

// bf16 hi/lo activations (zero-init pad rows stay zero)
__device__ __nv_bfloat16 g_qin_h[MQ * DMODEL],  g_qin_l[MQ * DMODEL];
__device__ __nv_bfloat16 g_kin_h[MKP * DMODEL], g_kin_l[MKP * DMODEL];
__device__ __nv_bfloat16 g_att_h[MQ * DMODEL],  g_att_l[MQ * DMODEL];
__device__ __nv_bfloat16 g_h1_h[MST * DMODEL],  g_h1_l[MST * DMODEL];
__device__ __nv_bfloat16 g_f1_h[MST * FFND],    g_f1_l[MST * FFND];
__device__ __nv_bfloat16 g_yin_h[2048 * DMODEL], g_yin_l[2048 * DMODEL];

// bf16 hi/lo weights in ORIGINAL [K,N] layout (no transpose needed)
__device__ __nv_bfloat16 g_wq_h[8 * DMODEL * DMODEL], g_wq_l[8 * DMODEL * DMODEL];
__device__ __nv_bfloat16 g_wk_h[8 * DMODEL * DMODEL], g_wk_l[8 * DMODEL * DMODEL];
__device__ __nv_bfloat16 g_wv_h[8 * DMODEL * DMODEL], g_wv_l[8 * DMODEL * DMODEL];
__device__ __nv_bfloat16 g_wo_h[8 * DMODEL * DMODEL], g_wo_l[8 * DMODEL * DMODEL];
__device__ __nv_bfloat16 g_w1_h[8 * DMODEL * FFND],   g_w1_l[8 * DMODEL * FFND];
__device__ __nv_bfloat16 g_w2_h[8 * FFND * DMODEL],   g_w2_l[8 * FFND * DMODEL];
__device__ __nv_bfloat16 g_wout_h[DMODEL * OUTD],     g_wout_l[DMODEL * OUTD];

// ---------------------------------------------------------------------------
// split helpers
// ---------------------------------------------------------------------------
__device__ __forceinline__ void split1(float v, __nv_bfloat16& h, __nv_bfloat16& l) {
    h = __float2bfloat16(v);
    l = __float2bfloat16(v - __bfloat162float(h));
}
__device__ __forceinline__ void split_store4(float4 o, __nv_bfloat16* hi,
                                             __nv_bfloat16* lo, size_t idx) {
    __nv_bfloat16 h0, h1, h2, h3, l0, l1, l2, l3;
    split1(o.x, h0, l0); split1(o.y, h1, l1);
    split1(o.z, h2, l2); split1(o.w, h3, l3);
    *(__nv_bfloat162*)&hi[idx]     = __halves2bfloat162(h0, h1);
    *(__nv_bfloat162*)&hi[idx + 2] = __halves2bfloat162(h2, h3);
    *(__nv_bfloat162*)&lo[idx]     = __halves2bfloat162(l0, l1);
    *(__nv_bfloat162*)&lo[idx + 2] = __halves2bfloat162(l2, l3);
}

// plain fp32 -> hi/lo split (weights, n multiple of 4)
__global__ void cvt_kernel(const float* __restrict__ src, __nv_bfloat16* __restrict__ hi,
                           __nv_bfloat16* __restrict__ lo, int n4) {
    int i = blockIdx.x * blockDim.x + threadIdx.x;
    if (i >= n4) return;
    float4 v = *(const float4*)&src[(size_t)i * 4];
    split_store4(v, hi, lo, (size_t)i * 4);
}

// ---------------------------------------------------------------------------
// small utility kernels
// ---------------------------------------------------------------------------
__global__ void inproj_kernel(const float* __restrict__ inp,
                              const float* __restrict__ w,
                              float* __restrict__ xout) {
    int t = blockIdx.x, b = blockIdx.y;
    __shared__ float sh[80];
    int tid = threadIdx.x;
    if (tid < 80) sh[tid] = inp[((size_t)b * 1040 + t) * 80 + tid];
    __syncthreads();
    float s = 0.f;
#pragma unroll 16
    for (int k = 0; k < 80; k++) s += sh[k] * w[k * 128 + tid];
    xout[(((size_t)(t >> 2)) * NB + b) * DMODEL + (t & 3) * 128 + tid] = s;
}

__global__ void state_init_kernel(const float* __restrict__ x, float* __restrict__ st) {
    int i = blockIdx.x * blockDim.x + threadIdx.x;
    if (i >= STROWS * NB * DMODEL) return;
    int d = i & 511;
    int b = (i >> 9) & 7;
    int r = i >> 12;
    int src = (r < 64) ? (((r >> 2) + 1) * 16 + (r & 3)) : (r - 64);
    st[i] = x[((size_t)src * NB + b) * DMODEL + d];
}

__global__ void mems0_kernel(const float* __restrict__ x,
                             __nv_bfloat16* __restrict__ kh, __nv_bfloat16* __restrict__ kl) {
    int i = blockIdx.x * blockDim.x + threadIdx.x;
    if (i >= NMEMS * NB * DMODEL) return;
    int d = i & 511;
    int b = (i >> 9) & 7;
    int s = i >> 12;
    float acc = 0.f;
    size_t base = ((size_t)(s * 16) * NB + b) * DMODEL + d;
    for (int t = 0; t < 16; t++) acc += x[base + (size_t)t * NB * DMODEL];
    acc *= (1.0f / 16.0f);
    split1(acc, kh[i], kl[i]);
}

__global__ void summary_kernel(const float* __restrict__ qin,
                               __nv_bfloat16* __restrict__ qh, __nv_bfloat16* __restrict__ ql) {
    int i = blockIdx.x * blockDim.x + threadIdx.x;
    if (i >= NSEG * NB * DMODEL) return;
    int d = i & 511;
    int b = (i >> 9) & 7;
    int s = i >> 12;
    float acc = 0.f;
    size_t base = ((size_t)(64 + s * 16) * NB + b) * DMODEL + d;
    for (int t = 0; t < 16; t++) acc += qin[base + (size_t)t * NB * DMODEL];
    acc *= (1.0f / 16.0f);
    size_t o = (size_t)STROWS * NB * DMODEL + i;
    split1(acc, qh[o], ql[o]);
}

__global__ void mems_tanh_kernel(const float* __restrict__ out, const float* __restrict__ bo,
                                 __nv_bfloat16* __restrict__ kh, __nv_bfloat16* __restrict__ kl) {
    int i = blockIdx.x * blockDim.x + threadIdx.x;
    if (i >= NMEMS * NB * DMODEL) return;
    float v = tanhf(out[(size_t)STROWS * NB * DMODEL + i] + bo[i & 511]);
    split1(v, kh[i], kl[i]);
}

__global__ void ytrans_kernel(const float* __restrict__ st,
                              __nv_bfloat16* __restrict__ yh, __nv_bfloat16* __restrict__ yl) {
    int i = blockIdx.x * blockDim.x + threadIdx.x;
    if (i >= 2048 * DMODEL) return;
    int d = i & 511;
    int m = i >> 9;
    int b = m >> 8;
    int t = m & 255;
    float v = st[((size_t)(64 + t) * NB + b) * DMODEL + d];
    split1(v, yh[i], yl[i]);
}

__global__ void lr_kernel(const int* __restrict__ lengths, float* __restrict__ out) {
    int b = threadIdx.x;
    if (b < 8) out[8u * 256u * 1024u + b] = (float)(lengths[b] >> 2);
}

// ---------------------------------------------------------------------------
// LayerNorm
// ---------------------------------------------------------------------------
template <int N>
__global__ __launch_bounds__(128) void ln4_kernel(const float* __restrict__ in,
                                                  const float* __restrict__ colbias,
                                                  const float* __restrict__ addin,
                                                  float* __restrict__ outsum,
                                                  float* __restrict__ outln,
                                                  __nv_bfloat16* __restrict__ oh1,
                                                  __nv_bfloat16* __restrict__ ol1,
                                                  __nv_bfloat16* __restrict__ oh2,
                                                  __nv_bfloat16* __restrict__ ol2,
                                                  const float* __restrict__ g,
                                                  const float* __restrict__ be) {
    constexpr int NV = N / 512;
    __shared__ float red[4];
    __shared__ float stat[2];
    int row = blockIdx.x, tid = threadIdx.x;
    size_t base = (size_t)row * N;
    float4 v[NV];
    float s = 0.f;
#pragma unroll
    for (int i = 0; i < NV; i++) {
        int c = (i * 128 + tid) * 4;
        float4 a = *(const float4*)&in[base + c];
        if (colbias) {
            float4 cb = *(const float4*)&colbias[c];
            a.x += cb.x; a.y += cb.y; a.z += cb.z; a.w += cb.w;
        }
        if (addin) {
            float4 r2 = *(const float4*)&addin[base + c];
            a.x += r2.x; a.y += r2.y; a.z += r2.z; a.w += r2.w;
        }
        v[i] = a;
        s += a.x + a.y + a.z + a.w;
    }
    for (int o = 16; o; o >>= 1) s += __shfl_xor_sync(0xffffffffu, s, o);
    if ((tid & 31) == 0) red[tid >> 5] = s;
    __syncthreads();
    if (tid == 0) stat[0] = (red[0] + red[1] + red[2] + red[3]) * (1.0f / N);
    __syncthreads();
    float mean = stat[0];
    float vs = 0.f;
#pragma unroll
    for (int i = 0; i < NV; i++) {
        float dx = v[i].x - mean, dy = v[i].y - mean, dz = v[i].z - mean, dw = v[i].w - mean;
        vs += dx * dx + dy * dy + dz * dz + dw * dw;
    }
    for (int o = 16; o; o >>= 1) vs += __shfl_xor_sync(0xffffffffu, vs, o);
    if ((tid & 31) == 0) red[tid >> 5] = vs;
    __syncthreads();
    if (tid == 0) stat[1] = rsqrtf((red[0] + red[1] + red[2] + red[3]) * (1.0f / N) + 1e-5f);
    __syncthreads();
    float rstd = stat[1];
#pragma unroll
    for (int i = 0; i < NV; i++) {
        int c = (i * 128 + tid) * 4;
        if (outsum) *(float4*)&outsum[base + c] = v[i];
        float4 gv = *(const float4*)&g[c];
        float4 bv = *(const float4*)&be[c];
        float4 o;
        o.x = (v[i].x - mean) * rstd * gv.x + bv.x;
        o.y = (v[i].y - mean) * rstd * gv.y + bv.y;
        o.z = (v[i].z - mean) * rstd * gv.z + bv.z;
        o.w = (v[i].w - mean) * rstd * gv.w + bv.w;
        if (outln) *(float4*)&outln[base + c] = o;
        if (oh1) split_store4(o, oh1, ol1, base + c);
        if (oh2) split_store4(o, oh2, ol2, base + c);
    }
}

// ---------------------------------------------------------------------------
// WMMA bf16x3 GEMM v3: C[M,N] = Ah@Bh + Al@Bh + Ah@Bl (fp32 acc)
// A: [M,K] row-major bf16 hi/lo (smem ld=40, row_major frags).
// B: [K,N] row-major bf16 hi/lo — ORIGINAL weight layout (smem ld=BN+8,
//    row_major matrix_b frags; layout proven in round 6).
// CTA 128xBN, 128 threads = 4 warps (2x2). BN=128: warp 64x64; BN=64: 64x32.
// EPI: fused bias+relu+split epilogue writing bf16 hi/lo (FFN1).
// M%128==0, N%BN==0, K%32==0.
// ---------------------------------------------------------------------------
#define GLD 40

template <int BN, bool EPI>
__device__ __forceinline__ void bgemm_w_body(const __nv_bfloat16* __restrict__ Ah,
                                             const __nv_bfloat16* __restrict__ Al,
                                             const __nv_bfloat16* __restrict__ Bh,
                                             const __nv_bfloat16* __restrict__ Bl,
                                             float* __restrict__ C,
                                             const float* __restrict__ bias,
                                             __nv_bfloat16* __restrict__ Oh,
                                             __nv_bfloat16* __restrict__ Ol,
                                             int M, int N, int K) {
    constexpr int LDB = BN + 8;
    constexpr int JF = BN / 32;         // B frags per warp (4 or 2)
    constexpr int NBI = BN / 32;        // B uint4 loads per thread (4 or 2)
    __shared__ __align__(16) __nv_bfloat16 sA[2][128 * GLD];
    __shared__ __align__(16) __nv_bfloat16 sB[2][32 * LDB];
    int tid = threadIdx.x;
    int wid = tid >> 5;
    int wm = wid >> 1, wn = wid & 1;
    size_t row0 = (size_t)blockIdx.y * 128;
    size_t col0 = (size_t)blockIdx.x * BN;

    const __nv_bfloat16* Ap[3] = {Ah, Al, Ah};
    const __nv_bfloat16* Bp[3] = {Bh, Bh, Bl};

    wmma::fragment<wmma::accumulator, 16, 16, 16, float> acc[4][JF];
#pragma unroll
    for (int i = 0; i < 4; i++)
#pragma unroll
        for (int j = 0; j < JF; j++) wmma::fill_fragment(acc[i][j], 0.f);

    int Kc = K >> 5;
    int total = 3 * Kc;

    uint4 a_st[4], b_st[NBI];
    // preload chunk 0
#pragma unroll
    for (int i = 0; i < 4; i++) {
        int id = tid + i * 128;
        a_st[i] = *(const uint4*)(Ap[0] + (row0 + (id >> 2)) * (size_t)K + (id & 3) * 8);
    }
#pragma unroll
    for (int i = 0; i < NBI; i++) {
        int id = tid + i * 128;
        int brow = id / (BN / 8), bc = id % (BN / 8);
        b_st[i] = *(const uint4*)(Bp[0] + (size_t)brow * N + col0 + bc * 8);
    }
#pragma unroll
    for (int i = 0; i < 4; i++) {
        int id = tid + i * 128;
        *(uint4*)&sA[0][(id >> 2) * GLD + (id & 3) * 8] = a_st[i];
    }
#pragma unroll
    for (int i = 0; i < NBI; i++) {
        int id = tid + i * 128;
        int brow = id / (BN / 8), bc = id % (BN / 8);
        *(uint4*)&sB[0][brow * LDB + bc * 8] = b_st[i];
    }
    __syncthreads();

    int buf = 0;
    for (int it = 0; it < total; it++) {
        if (it + 1 < total) {
            int p = (it + 1) / Kc;
            int k0 = ((it + 1) % Kc) << 5;
#pragma unroll
            for (int i = 0; i < 4; i++) {
                int id = tid + i * 128;
                a_st[i] = *(const uint4*)(Ap[p] + (row0 + (id >> 2)) * (size_t)K + k0 + (id & 3) * 8);
            }
#pragma unroll
            for (int i = 0; i < NBI; i++) {
                int id = tid + i * 128;
                int brow = id / (BN / 8), bc = id % (BN / 8);
                b_st[i] = *(const uint4*)(Bp[p] + (size_t)(k0 + brow) * N + col0 + bc * 8);
            }
        }
        const __nv_bfloat16* a_ = sA[buf];
        const __nv_bfloat16* b_ = sB[buf];
#pragma unroll
        for (int ks = 0; ks < 2; ks++) {
            wmma::fragment<wmma::matrix_a, 16, 16, 16, __nv_bfloat16, wmma::row_major> af[4];
            wmma::fragment<wmma::matrix_b, 16, 16, 16, __nv_bfloat16, wmma::row_major> bf[JF];
#pragma unroll
            for (int i = 0; i < 4; i++)
                wmma::load_matrix_sync(af[i], a_ + (wm * 64 + i * 16) * GLD + ks * 16, GLD);
#pragma unroll
            for (int j = 0; j < JF; j++)
                wmma::load_matrix_sync(bf[j], b_ + (ks * 16) * LDB + wn * (BN / 2) + j * 16, LDB);
#pragma unroll
            for (int i = 0; i < 4; i++)
#pragma unroll
                for (int j = 0; j < JF; j++)
                    wmma::mma_sync(acc[i][j], af[i], bf[j], acc[i][j]);
        }
        if (it + 1 < total) {
            buf ^= 1;
#pragma unroll
            for (int i = 0; i < 4; i++) {
                int id = tid + i * 128;
                *(uint4*)&sA[buf][(id >> 2) * GLD + (id & 3) * 8] = a_st[i];
            }
#pragma unroll
            for (int i = 0; i < NBI; i++) {
                int id = tid + i * 128;
                int brow = id / (BN / 8), bc = id % (BN / 8);
                *(uint4*)&sB[buf][brow * LDB + bc * 8] = b_st[i];
            }
            __syncthreads();
        }
    }

    if (!EPI) {
#pragma unroll
        for (int i = 0; i < 4; i++)
#pragma unroll
            for (int j = 0; j < JF; j++)
                wmma::store_matrix_sync(C + (row0 + wm * 64 + i * 16) * N + col0 + wn * (BN / 2) + j * 16,
                                        acc[i][j], N, wmma::mem_row_major);
    } else {
        // fused bias + relu + bf16 hi/lo split epilogue, staged through sA
        __syncthreads();
        float* stage = (float*)&sA[0][0];   // 128 x 36 fp32 = 18432 B (fits in sA)
#pragma unroll
        for (int j = 0; j < JF; j++) {
#pragma unroll
            for (int i = 0; i < 4; i++)
                wmma::store_matrix_sync(stage + (wm * 64 + i * 16) * 36 + wn * 16,
                                        acc[i][j], 36, wmma::mem_row_major);
            __syncthreads();
            for (int e = tid; e < 128 * 16; e += 128) {
                int row = e >> 4;
                int c = (e & 15) * 2;          // 0..30 within 32 staged cols
                int strip = c >> 4;
                int within = c & 15;
                int gc = (int)col0 + strip * (BN / 2) + j * 16 + within;
                float v0 = stage[row * 36 + c];
                float v1 = stage[row * 36 + c + 1];
                v0 = fmaxf(v0 + bias[gc], 0.f);
                v1 = fmaxf(v1 + bias[gc + 1], 0.f);
                __nv_bfloat16 h0, l0, h1, l1;
                split1(v0, h0, l0);
                split1(v1, h1, l1);
                size_t ob = (row0 + row) * (size_t)N + gc;
                *(__nv_bfloat162*)&Oh[ob] = __halves2bfloat162(h0, h1);
                *(__nv_bfloat162*)&Ol[ob] = __halves2bfloat162(l0, l1);
            }
            __syncthreads();
        }
    }
}

template <int BN, bool EPI>
__global__ __launch_bounds__(128) void bgemm_w(const __nv_bfloat16* Ah, const __nv_bfloat16* Al,
                                               const __nv_bfloat16* Bh, const __nv_bfloat16* Bl,
                                               float* C, const float* bias,
                                               __nv_bfloat16* Oh, __nv_bfloat16* Ol,
                                               int M, int N, int K) {
    bgemm_w_body<BN, EPI>(Ah, Al, Bh, Bl, C, bias, Oh, Ol, M, N, K);
}

__global__ __launch_bounds__(128) void bgemm_w_qkv(
    const __nv_bfloat16* qh, const __nv_bfloat16* ql,
    const __nv_bfloat16* kh, const __nv_bfloat16* kl,
    const __nv_bfloat16* wqh, const __nv_bfloat16* wql,
    const __nv_bfloat16* wkh, const __nv_bfloat16* wkl,
    const __nv_bfloat16* wvh, const __nv_bfloat16* wvl,
    float* q, float* k, float* v) {
    int z = blockIdx.z;
    const __nv_bfloat16* Ah = (z == 0) ? qh : kh;
    const __nv_bfloat16* Al = (z == 0) ? ql : kl;
    const __nv_bfloat16* Bh = (z == 0) ? wqh : (z == 1) ? wkh : wvh;
    const __nv_bfloat16* Bl = (z == 0) ? wql : (z == 1) ? wkl : wvl;
    float* C = (z == 0) ? q : (z == 1) ? k : v;
    bgemm_w_body<64, false>(Ah, Al, Bh, Bl, C, nullptr, nullptr, nullptr, 2688, DMODEL, DMODEL);
}

// ---------------------------------------------------------------------------
// Sparse attention (unchanged from round 13 — passing).
// ---------------------------------------------------------------------------
__global__ __launch_bounds__(128) void attn_sparse(const float* __restrict__ Qb,
                                                   const float* __restrict__ Kb,
                                                   const float* __restrict__ Vb,
                                                   const float* __restrict__ bq,
                                                   const float* __restrict__ bk,
                                                   const float* __restrict__ bv,
                                                   const int* __restrict__ lengths,
                                                   __nv_bfloat16* __restrict__ Oh,
                                                   __nv_bfloat16* __restrict__ Ol) {
    __shared__ float qs[21][66];
    __shared__ float kT[64][66];
    __shared__ float vs[64][66];
    __shared__ float sc[21][66];
    int i = blockIdx.x, h = blockIdx.y, b = blockIdx.z;
    int tid = threadIdx.x, lane = tid & 31, wid = tid >> 5;

    int nm = min(i, 4);
    int ms = i - nm;
    int ss = max(16 * i - 32, 0);
    int se = min(16 * i + 16, 256);
    int cnt = nm + 4 + (se - ss);

    int lrb = lengths[b] >> 2;
    int maxlr = 0;
#pragma unroll
    for (int t = 0; t < 8; t++) maxlr = max(maxlr, lengths[t] >> 2);
    int klen = 335 - (maxlr - lrb);

    for (int idx = tid; idx < 64 * 66; idx += 128) ((float*)vs)[idx] = 0.f;
    __syncthreads();

    {
        int j = tid >> 1, half = tid & 1;
        if (j < cnt) {
            int kc = (j < nm) ? (ms + j)
                   : (j < nm + 4) ? (15 + 4 * i + (j - nm))
                   : (79 + ss + (j - nm - 4));
            const float* kr = Kb + ((size_t)kc * NB + b) * DMODEL + h * 64 + half * 32;
            const float* vr = Vb + ((size_t)kc * NB + b) * DMODEL + h * 64 + half * 32;
            const float* bkh = bk + h * 64 + half * 32;
            const float* bvh = bv + h * 64 + half * 32;
#pragma unroll
            for (int d = 0; d < 32; d++) {
                kT[half * 32 + d][j] = kr[d] + bkh[d];
                vs[j][half * 32 + d] = vr[d] + bvh[d];
            }
        }
    }
    for (int idx = tid; idx < 21 * 64; idx += 128) {
        int r = idx >> 6, d = idx & 63;
        int g = (r < 4) ? (4 * i + r) : (r < 20) ? (64 + 16 * i + (r - 4)) : (320 + i);
        qs[r][d] = (Qb[((size_t)g * NB + b) * DMODEL + h * 64 + d] + bq[h * 64 + d]) * 0.125f;
    }
    __syncthreads();

    for (int rp = 0; rp < 6; rp++) {
        int r = rp * 4 + wid;
        if (r < 21) {
            unsigned long long acc2 = 0ull;
#pragma unroll
            for (int d = 0; d < 64; d++) {
                unsigned long long qp;
                PACK2(qp, qs[r][d]);
                FMA2(acc2, qp, *(const unsigned long long*)&kT[d][2 * lane]);
            }
            float2 t = *(float2*)&acc2;
#pragma unroll
            for (int u = 0; u < 2; u++) {
                int j = 2 * lane + u;
                float dot = u ? t.y : t.x;
                bool ok = (j < cnt);
                if (ok) {
                    int kc = (j < nm) ? (ms + j)
                           : (j < nm + 4) ? (15 + 4 * i + (j - nm))
                           : (79 + ss + (j - nm - 4));
                    ok = (kc < klen) && !(r == 20 && j < nm);
                }
                sc[r][j] = ok ? dot : -1e8f;
            }
        }
    }
    __syncthreads();

    for (int r = wid; r < 21; r += 4) {
        float a = sc[r][lane], c = sc[r][lane + 32];
        float m = fmaxf(a, c);
        for (int o = 16; o; o >>= 1) m = fmaxf(m, __shfl_xor_sync(0xffffffffu, m, o));
        float e1 = __expf(a - m), e2 = __expf(c - m);
        float s = e1 + e2;
        for (int o = 16; o; o >>= 1) s += __shfl_xor_sync(0xffffffffu, s, o);
        float inv = 1.0f / s;
        sc[r][lane] = e1 * inv;
        sc[r][lane + 32] = e2 * inv;
    }
    __syncthreads();

    for (int rp = 0; rp < 6; rp++) {
        int r = rp * 4 + wid;
        if (r < 21) {
            unsigned long long acc2 = 0ull;
#pragma unroll
            for (int j = 0; j < 64; j++) {
                unsigned long long pp;
                PACK2(pp, sc[r][j]);
                FMA2(acc2, pp, *(const unsigned long long*)&vs[j][2 * lane]);
            }
            float2 t = *(float2*)&acc2;
            int g = (r < 4) ? (4 * i + r) : (r < 20) ? (64 + 16 * i + (r - 4)) : (320 + i);
            size_t base = ((size_t)g * NB + b) * DMODEL + h * 64 + 2 * lane;
            __nv_bfloat16 h0, l0, h1, l1;
            split1(t.x, h0, l0);
            split1(t.y, h1, l1);
            *(__nv_bfloat162*)&Oh[base] = __halves2bfloat162(h0, h1);
            *(__nv_bfloat162*)&Ol[base] = __halves2bfloat162(l0, l1);
        }
    }
}

// ---------------------------------------------------------------------------
// Host driver
// ---------------------------------------------------------------------------
extern "C" void kernel_launch(void* const* d_in, const int* in_sizes, int n_in,
                              void* d_out, int out_size) {
    const float* input   = (const float*)d_in[0];
    const int*   lengths = (const int*)d_in[1];
    const float* w_in    = (const float*)d_in[2];
    const float* ln_in_g = (const float*)d_in[3];
    const float* ln_in_b = (const float*)d_in[4];
    const float* wq      = (const float*)d_in[5];
    const float* bq      = (const float*)d_in[6];
    const float* wk      = (const float*)d_in[7];
    const float* bk      = (const float*)d_in[8];
    const float* wv      = (const float*)d_in[9];
    const float* bv      = (const float*)d_in[10];
    const float* wo      = (const float*)d_in[11];
    const float* bo      = (const float*)d_in[12];
    const float* ff_ln_g = (const float*)d_in[13];
    const float* ff_ln_b = (const float*)d_in[14];
    const float* w1      = (const float*)d_in[15];
    const float* b1      = (const float*)d_in[16];
    const float* w2      = (const float*)d_in[17];
    const float* b2      = (const float*)d_in[18];
    const float* ln_out_g = (const float*)d_in[19];
    const float* ln_out_b = (const float*)d_in[20];
    const float* w_out   = (const float*)d_in[21];
    const float* b_out   = (const float*)d_in[22];
    const float* lng     = (const float*)d_in[23];
    const float* lnb     = (const float*)d_in[24];
    float* out = (float*)d_out;

    float *px, *pstate, *pstate2, *pqin, *pq, *pk, *pv, *pout2, *pf2r, *pyt;
    cudaGetSymbolAddress((void**)&px, g_x);
    cudaGetSymbolAddress((void**)&pstate, g_state);
    cudaGetSymbolAddress((void**)&pstate2, g_state2);
    cudaGetSymbolAddress((void**)&pqin, g_qin);
    cudaGetSymbolAddress((void**)&pq, g_q);
    cudaGetSymbolAddress((void**)&pk, g_k);
    cudaGetSymbolAddress((void**)&pv, g_v);
    cudaGetSymbolAddress((void**)&pout2, g_out);
    cudaGetSymbolAddress((void**)&pf2r, g_f2raw);
    cudaGetSymbolAddress((void**)&pyt, g_yt);

    __nv_bfloat16 *qinh, *qinl, *kinh, *kinl, *atth, *attl, *h1h, *h1l, *f1h, *f1l, *yinh, *yinl;
    cudaGetSymbolAddress((void**)&qinh, g_qin_h); cudaGetSymbolAddress((void**)&qinl, g_qin_l);
    cudaGetSymbolAddress((void**)&kinh, g_kin_h); cudaGetSymbolAddress((void**)&kinl, g_kin_l);
    cudaGetSymbolAddress((void**)&atth, g_att_h); cudaGetSymbolAddress((void**)&attl, g_att_l);
    cudaGetSymbolAddress((void**)&h1h, g_h1_h);   cudaGetSymbolAddress((void**)&h1l, g_h1_l);
    cudaGetSymbolAddress((void**)&f1h, g_f1_h);   cudaGetSymbolAddress((void**)&f1l, g_f1_l);
    cudaGetSymbolAddress((void**)&yinh, g_yin_h); cudaGetSymbolAddress((void**)&yinl, g_yin_l);

    __nv_bfloat16 *wqh, *wql, *wkh, *wkl, *wvh, *wvl, *woh, *wol, *w1h, *w1l, *w2h, *w2l, *wouth, *woutl;
    cudaGetSymbolAddress((void**)&wqh, g_wq_h);  cudaGetSymbolAddress((void**)&wql, g_wq_l);
    cudaGetSymbolAddress((void**)&wkh, g_wk_h);  cudaGetSymbolAddress((void**)&wkl, g_wk_l);
    cudaGetSymbolAddress((void**)&wvh, g_wv_h);  cudaGetSymbolAddress((void**)&wvl, g_wv_l);
    cudaGetSymbolAddress((void**)&woh, g_wo_h);  cudaGetSymbolAddress((void**)&wol, g_wo_l);
    cudaGetSymbolAddress((void**)&w1h, g_w1_h);  cudaGetSymbolAddress((void**)&w1l, g_w1_l);
    cudaGetSymbolAddress((void**)&w2h, g_w2_h);  cudaGetSymbolAddress((void**)&w2l, g_w2_l);
    cudaGetSymbolAddress((void**)&wouth, g_wout_h); cudaGetSymbolAddress((void**)&woutl, g_wout_l);

    // weight hi/lo split in ORIGINAL [K,N] layout (no transpose). 7 launches.
    const int WQN4 = 8 * DMODEL * DMODEL / 4;   // 524288
    const int W1N4 = 8 * DMODEL * FFND / 4;     // 2097152
    cvt_kernel<<<(WQN4 + 255) / 256, 256>>>(wq, wqh, wql, WQN4);
    cvt_kernel<<<(WQN4 + 255) / 256, 256>>>(wk, wkh, wkl, WQN4);
    cvt_kernel<<<(WQN4 + 255) / 256, 256>>>(wv, wvh, wvl, WQN4);
    cvt_kernel<<<(WQN4 + 255) / 256, 256>>>(wo, woh, wol, WQN4);
    cvt_kernel<<<(W1N4 + 255) / 256, 256>>>(w1, w1h, w1l, W1N4);
    cvt_kernel<<<(W1N4 + 255) / 256, 256>>>(w2, w2h, w2l, W1N4);
    cvt_kernel<<<(DMODEL * OUTD / 4 + 255) / 256, 256>>>(w_out, wouth, woutl, DMODEL * OUTD / 4);

    inproj_kernel<<<dim3(1040, 8), 128>>>(input, w_in, px);
    state_init_kernel<<<(STROWS * NB * DMODEL + 255) / 256, 256>>>(px, pstate);
    mems0_kernel<<<(NMEMS * NB * DMODEL + 255) / 256, 256>>>(px, kinh, kinl);

    const size_t WS = (size_t)DMODEL * DMODEL;
    const size_t W1S = (size_t)DMODEL * FFND;
    const size_t KIN_OFF = (size_t)NMEMS * NB * DMODEL;

    for (int l = 0; l < 8; l++) {
        ln4_kernel<512><<<STROWS * NB, 128>>>(pstate, nullptr, nullptr, nullptr, pqin,
                                              qinh, qinl, kinh + KIN_OFF, kinl + KIN_OFF,
                                              ln_in_g + l * DMODEL, ln_in_b + l * DMODEL);
        summary_kernel<<<(NSEG * NB * DMODEL + 255) / 256, 256>>>(pqin, qinh, qinl);
        bgemm_w_qkv<<<dim3(8, 21, 3), 128>>>(qinh, qinl, kinh, kinl,
                                             wqh + l * WS, wql + l * WS,
                                             wkh + l * WS, wkl + l * WS,
                                             wvh + l * WS, wvl + l * WS,
                                             pq, pk, pv);
        attn_sparse<<<dim3(16, 8, 8), 128>>>(pq, pk, pv,
                                             bq + l * DMODEL, bk + l * DMODEL, bv + l * DMODEL,
                                             lengths, atth, attl);
        bgemm_w<64, false><<<dim3(8, 21), 128>>>(atth, attl, woh + l * WS, wol + l * WS,
                                                 pout2, nullptr, nullptr, nullptr,
                                                 MQ, DMODEL, DMODEL);
        mems_tanh_kernel<<<(NMEMS * NB * DMODEL + 255) / 256, 256>>>(pout2, bo + l * DMODEL,
                                                                     kinh, kinl);
        ln4_kernel<512><<<STROWS * NB, 128>>>(pout2, bo + l * DMODEL, pstate, pstate2, nullptr,
                                              h1h, h1l, nullptr, nullptr,
                                              ff_ln_g + l * DMODEL, ff_ln_b + l * DMODEL);
        // FFN1 with fused bias+relu+split epilogue -> f1 hi/lo (no fp32 roundtrip)
        bgemm_w<128, true><<<dim3(16, 20), 128>>>(h1h, h1l, w1h + l * W1S, w1l + l * W1S,
                                                  nullptr, b1 + l * FFND, f1h, f1l,
                                                  MST, FFND, DMODEL);
        bgemm_w<64, false><<<dim3(8, 20), 128>>>(f1h, f1l, w2h + l * W1S, w2l + l * W1S,
                                                 pf2r, nullptr, nullptr, nullptr,
                                                 MST, DMODEL, FFND);
        ln4_kernel<512><<<STROWS * NB, 128>>>(pf2r, b2 + l * DMODEL, pstate2, nullptr, pstate,
                                              nullptr, nullptr, nullptr, nullptr,
                                              ln_out_g + l * DMODEL, ln_out_b + l * DMODEL);
    }

    ytrans_kernel<<<(2048 * DMODEL + 255) / 256, 256>>>(pstate, yinh, yinl);
    bgemm_w<64, false><<<dim3(16, 16), 128>>>(yinh, yinl, wouth, woutl, pyt,
                                              nullptr, nullptr, nullptr, 2048, OUTD, DMODEL);
    ln4_kernel<1024><<<2048, 128>>>(pyt, b_out, nullptr, nullptr, out,
                                    nullptr, nullptr, nullptr, nullptr, lng, lnb);

    if (out_size >= 8 * 256 * 1024 + 8) {
        lr_kernel<<<1, 8>>>(lengths, out);
    }
}